// round 8
// baseline (speedup 1.0000x reference)
#include <cuda_runtime.h>
#include <cuda_bf16.h>
#include <math.h>
#include <stdint.h>

#define B_ 8
#define N_ 1024
#define E_ 768
#define H_ 12
#define D_ 64
#define M_ (B_*N_)   // 8192

// ---------------------------------------------------------------------------
// Scratch (__device__ globals; no allocations allowed)
// ---------------------------------------------------------------------------
__device__ __nv_bfloat16 g_xh[(size_t)M_ * E_];
__device__ __nv_bfloat16 g_xl[(size_t)M_ * E_];
__device__ __nv_bfloat16 g_wqh[(size_t)3*E_ * E_];
__device__ __nv_bfloat16 g_wql[(size_t)3*E_ * E_];
__device__ __nv_bfloat16 g_wph[(size_t)E_ * E_];
__device__ __nv_bfloat16 g_wpl[(size_t)E_ * E_];
__device__ __nv_bfloat16 g_aoh[(size_t)M_ * E_];
__device__ __nv_bfloat16 g_aol[(size_t)M_ * E_];
__device__ __nv_bfloat16 g_qh2[(size_t)B_*H_*N_*D_];
__device__ __nv_bfloat16 g_ql2[(size_t)B_*H_*N_*D_];
__device__ __nv_bfloat16 g_kh2[(size_t)B_*H_*N_*D_];
__device__ __nv_bfloat16 g_kl2[(size_t)B_*H_*N_*D_];
__device__ __nv_bfloat16 g_vth[(size_t)B_*H_*D_*N_];
__device__ __nv_bfloat16 g_vtl[(size_t)B_*H_*D_*N_];

// ---------------------------------------------------------------------------
// PTX helpers
// ---------------------------------------------------------------------------
__device__ __forceinline__ uint32_t smem_u32(const void* p) {
    uint32_t a;
    asm("{ .reg .u64 t; cvta.to.shared.u64 t, %1; cvt.u32.u64 %0, t; }" : "=r"(a) : "l"(p));
    return a;
}
#define CPA16(dst, src) \
    asm volatile("cp.async.cg.shared.global [%0], [%1], 16;" :: "r"(dst), "l"(src) : "memory")
#define CP_COMMIT() asm volatile("cp.async.commit_group;" ::: "memory")
#define CP_WAIT1()  asm volatile("cp.async.wait_group 1;" ::: "memory")

__device__ __forceinline__ void ldsm_x4(uint32_t addr, uint32_t& r0, uint32_t& r1,
                                        uint32_t& r2, uint32_t& r3) {
    asm volatile("ldmatrix.sync.aligned.m8n8.x4.shared.b16 {%0,%1,%2,%3}, [%4];"
                 : "=r"(r0), "=r"(r1), "=r"(r2), "=r"(r3) : "r"(addr));
}
__device__ __forceinline__ void mma_bf16(float* c, const uint32_t* a, const uint32_t* b) {
    asm volatile("mma.sync.aligned.m16n8k16.row.col.f32.bf16.bf16.f32 "
        "{%0,%1,%2,%3}, {%4,%5,%6,%7}, {%8,%9}, {%0,%1,%2,%3};"
        : "+f"(c[0]), "+f"(c[1]), "+f"(c[2]), "+f"(c[3])
        : "r"(a[0]), "r"(a[1]), "r"(a[2]), "r"(a[3]), "r"(b[0]), "r"(b[1]));
}
__device__ __forceinline__ uint32_t pack_bf16x2(float lo, float hi) {
    __nv_bfloat162 t = __floats2bfloat162_rn(lo, hi);
    return *(uint32_t*)&t;
}
__device__ __forceinline__ void split2(float v0, float v1, uint32_t& hi, uint32_t& lo) {
    __nv_bfloat16 h0 = __float2bfloat16(v0), h1 = __float2bfloat16(v1);
    hi = (uint32_t)__bfloat16_as_ushort(h0) | ((uint32_t)__bfloat16_as_ushort(h1) << 16);
    lo = pack_bf16x2(v0 - __bfloat162float(h0), v1 - __bfloat162float(h1));
}

// ---------------------------------------------------------------------------
// convert kernels
// ---------------------------------------------------------------------------
__global__ void convert_split(const float4* __restrict__ in,
                              uint2* __restrict__ hi, uint2* __restrict__ lo, int n4)
{
    int i = blockIdx.x * blockDim.x + threadIdx.x;
    if (i >= n4) return;
    float4 v = in[i];
    uint2 H, L;
    split2(v.x, v.y, H.x, L.x);
    split2(v.z, v.w, H.y, L.y);
    hi[i] = H;
    lo[i] = L;
}

__global__ void convert_w_t(const float* __restrict__ W,
                            __nv_bfloat16* __restrict__ Th, __nv_bfloat16* __restrict__ Tl,
                            int K, int N)
{
    __shared__ float tile[32][33];
    int n0 = blockIdx.x * 32, k0 = blockIdx.y * 32;
    int tx = threadIdx.x, ty = threadIdx.y;
    for (int i = ty; i < 32; i += 8)
        tile[i][tx] = W[(size_t)(k0 + i) * N + n0 + tx];
    __syncthreads();
    for (int i = ty; i < 32; i += 8) {
        float v = tile[tx][i];
        __nv_bfloat16 h = __float2bfloat16(v);
        Th[(size_t)(n0 + i) * K + k0 + tx] = h;
        Tl[(size_t)(n0 + i) * K + k0 + tx] = __float2bfloat16(v - __bfloat162float(h));
    }
}

// ---------------------------------------------------------------------------
// GEMM mainloop: R4 schedule (2-stage, two syncs), strength-reduced addresses.
// ---------------------------------------------------------------------------
__device__ __forceinline__ void gemm_mainloop(
    uint32_t sbase, int tid, int lane, int wm, int wn,
    const __nv_bfloat16* __restrict__ Ah, const __nv_bfloat16* __restrict__ Al,
    const __nv_bfloat16* __restrict__ Bh, const __nv_bfloat16* __restrict__ Bl,
    int m0, int n0, int Ktot, float (&acc)[2][8][4])
{
    const int NCH = Ktot / 32;

    int rowa = tid >> 2, chunk = tid & 3;
    int rowb = rowa + 64;
    uint32_t soff0 = (uint32_t)(rowa * 64 + ((chunk ^ (rowa & 3)) * 16));
    uint32_t soff1 = (uint32_t)(rowb * 64 + ((chunk ^ (rowb & 3)) * 16));
    const char* pA0h = (const char*)(Ah + (size_t)(m0 + rowa) * Ktot + chunk * 8);
    const char* pA0l = (const char*)(Al + (size_t)(m0 + rowa) * Ktot + chunk * 8);
    const char* pB0h = (const char*)(Bh + (size_t)(n0 + rowa) * Ktot + chunk * 8);
    const char* pB0l = (const char*)(Bl + (size_t)(n0 + rowa) * Ktot + chunk * 8);
    const char* pA1h = (const char*)(Ah + (size_t)(m0 + rowb) * Ktot + chunk * 8);
    const char* pA1l = (const char*)(Al + (size_t)(m0 + rowb) * Ktot + chunk * 8);
    const char* pB1h = (const char*)(Bh + (size_t)(n0 + rowb) * Ktot + chunk * 8);
    const char* pB1l = (const char*)(Bl + (size_t)(n0 + rowb) * Ktot + chunk * 8);

    auto load_stage = [&](int st) {
        uint32_t sb = sbase + (uint32_t)st * 32768u;
        CPA16(sb +          soff0, pA0h);
        CPA16(sb +  8192u + soff0, pA0l);
        CPA16(sb + 16384u + soff0, pB0h);
        CPA16(sb + 24576u + soff0, pB0l);
        CPA16(sb +          soff1, pA1h);
        CPA16(sb +  8192u + soff1, pA1l);
        CPA16(sb + 16384u + soff1, pB1h);
        CPA16(sb + 24576u + soff1, pB1l);
        pA0h += 64; pA0l += 64; pB0h += 64; pB0l += 64;
        pA1h += 64; pA1l += 64; pB1h += 64; pB1l += 64;
    };

    uint32_t offA[2][2], offB[4][2];
    #pragma unroll
    for (int mi = 0; mi < 2; mi++) {
        int r = wm * 32 + mi * 16 + (lane & 15);
        #pragma unroll
        for (int ks = 0; ks < 2; ks++) {
            int c2 = ks * 2 + (lane >> 4);
            offA[mi][ks] = (uint32_t)(r * 64 + ((c2 ^ (r & 3)) * 16));
        }
    }
    #pragma unroll
    for (int p = 0; p < 4; p++) {
        int r = wn * 64 + p * 16 + (lane & 15);
        #pragma unroll
        for (int ks = 0; ks < 2; ks++) {
            int c2 = ks * 2 + (lane >> 4);
            offB[p][ks] = (uint32_t)(r * 64 + ((c2 ^ (r & 3)) * 16));
        }
    }

    auto compute_stage = [&](int st) {
        uint32_t sA = sbase + (uint32_t)st * 32768u;
        #pragma unroll
        for (int ks = 0; ks < 2; ks++) {
            uint32_t ah[2][4], al[2][4];
            #pragma unroll
            for (int mi = 0; mi < 2; mi++) {
                ldsm_x4(sA + offA[mi][ks], ah[mi][0], ah[mi][1], ah[mi][2], ah[mi][3]);
                ldsm_x4(sA + 8192u + offA[mi][ks], al[mi][0], al[mi][1], al[mi][2], al[mi][3]);
            }
            uint32_t bh[8][2], bl[8][2];
            #pragma unroll
            for (int p = 0; p < 4; p++) {
                uint32_t t0, t1, t2, t3;
                ldsm_x4(sA + 16384u + offB[p][ks], t0, t1, t2, t3);
                bh[2*p][0] = t0; bh[2*p][1] = t2; bh[2*p+1][0] = t1; bh[2*p+1][1] = t3;
                ldsm_x4(sA + 24576u + offB[p][ks], t0, t1, t2, t3);
                bl[2*p][0] = t0; bl[2*p][1] = t2; bl[2*p+1][0] = t1; bl[2*p+1][1] = t3;
            }
            #pragma unroll
            for (int mi = 0; mi < 2; mi++)
                #pragma unroll
                for (int ni = 0; ni < 8; ni++) {
                    mma_bf16(acc[mi][ni], ah[mi], bh[ni]);
                    mma_bf16(acc[mi][ni], ah[mi], bl[ni]);
                    mma_bf16(acc[mi][ni], al[mi], bh[ni]);
                }
        }
    };

    load_stage(0); CP_COMMIT();
    load_stage(1); CP_COMMIT();

    for (int ch = 0; ch < NCH; ch++) {
        CP_WAIT1();
        __syncthreads();
        compute_stage(ch & 1);
        __syncthreads();
        if (ch + 2 < NCH) load_stage(ch & 1);
        CP_COMMIT();
    }
}

// ---------------------------------------------------------------------------
// Fused QKV GEMM: bias + RoPE + hi/lo split + V-transpose epilogue.
// NOTE: V epilogue needs 128*129*4 = 66048 B smem (> 64KB pipeline usage);
// dynamic smem allocation must cover it (GEMM_SMEM = 66560).
// ---------------------------------------------------------------------------
__global__ __launch_bounds__(256, 2)
void tc_gemm_qkv(const __nv_bfloat16* __restrict__ Ah, const __nv_bfloat16* __restrict__ Al,
                 const __nv_bfloat16* __restrict__ Bh, const __nv_bfloat16* __restrict__ Bl,
                 const float* __restrict__ bias,
                 __nv_bfloat16* __restrict__ Qh, __nv_bfloat16* __restrict__ Ql,
                 __nv_bfloat16* __restrict__ Kh, __nv_bfloat16* __restrict__ Kl,
                 __nv_bfloat16* __restrict__ Vth, __nv_bfloat16* __restrict__ Vtl)
{
    extern __shared__ char smem[];
    uint32_t sbase = smem_u32(smem);
    int tid = threadIdx.x, lane = tid & 31, wid = tid >> 5;
    int wm = wid & 3, wn = wid >> 2;
    int m0 = blockIdx.y * 128, n0 = blockIdx.x * 128;

    float acc[2][8][4];
    #pragma unroll
    for (int mi = 0; mi < 2; mi++)
        #pragma unroll
        for (int ni = 0; ni < 8; ni++)
            #pragma unroll
            for (int e = 0; e < 4; e++) acc[mi][ni][e] = 0.f;

    gemm_mainloop(sbase, tid, lane, wm, wn, Ah, Al, Bh, Bl, m0, n0, E_, acc);
    __syncthreads();   // V branch reuses smem below

    #pragma unroll
    for (int ni = 0; ni < 8; ni++) {
        int col = n0 + wn * 64 + ni * 8 + (lane & 3) * 2;
        float2 bv = *(const float2*)&bias[col];
        #pragma unroll
        for (int mi = 0; mi < 2; mi++) {
            acc[mi][ni][0] += bv.x; acc[mi][ni][1] += bv.y;
            acc[mi][ni][2] += bv.x; acc[mi][ni][3] += bv.y;
        }
    }

    int sec = n0 / 768;
    int nsec = n0 - sec * 768;
    int b = m0 >> 10;
    int t_base = m0 & 1023;

    if (sec < 2) {
        int h = nsec / 64 + wn;
        int bh = b * H_ + h;
        float cs[8], sn[8];
        #pragma unroll
        for (int u = 0; u < 8; u++) {
            int d2 = (u >> 1) * 8 + (lane & 3) * 2 + (u & 1);
            float f = (float)h * exp2f(-(float)d2 * (13.287712379549449f / 32.0f));
            sincosf(f, &sn[u], &cs[u]);
        }
        __nv_bfloat16* Oh = (sec == 0) ? Qh : Kh;
        __nv_bfloat16* Ol = (sec == 0) ? Ql : Kl;
        const float scale = (sec == 0) ? 0.125f : 1.0f;

        #pragma unroll
        for (int mi = 0; mi < 2; mi++) {
            int rbase = wm * 32 + mi * 16 + (lane >> 2);
            #pragma unroll
            for (int eh = 0; eh < 2; eh++) {
                int t = t_base + rbase + eh * 8;
                size_t rowoff = ((size_t)bh * N_ + t) * (size_t)D_;
                #pragma unroll
                for (int ni = 0; ni < 4; ni++) {
                    float a0 = acc[mi][ni][eh*2+0], b0 = acc[mi][ni+4][eh*2+0];
                    float a1 = acc[mi][ni][eh*2+1], b1 = acc[mi][ni+4][eh*2+1];
                    int u0 = ni * 2, u1 = u0 + 1;
                    float lo0 = (a0 * cs[u0] - b0 * sn[u0]) * scale;
                    float hi0 = (b0 * cs[u0] + a0 * sn[u0]) * scale;
                    float lo1 = (a1 * cs[u1] - b1 * sn[u1]) * scale;
                    float hi1 = (b1 * cs[u1] + a1 * sn[u1]) * scale;
                    int d0 = ni * 8 + (lane & 3) * 2;
                    uint32_t H, L;
                    split2(lo0, lo1, H, L);
                    *(uint32_t*)(Oh + rowoff + d0) = H;
                    *(uint32_t*)(Ol + rowoff + d0) = L;
                    split2(hi0, hi1, H, L);
                    *(uint32_t*)(Oh + rowoff + d0 + 32) = H;
                    *(uint32_t*)(Ol + rowoff + d0 + 32) = L;
                }
            }
        }
    } else {
        float* sv = (float*)smem;
        #pragma unroll
        for (int mi = 0; mi < 2; mi++)
            #pragma unroll
            for (int ni = 0; ni < 8; ni++)
                #pragma unroll
                for (int e = 0; e < 4; e++) {
                    int col = wn * 64 + ni * 8 + (lane & 3) * 2 + (e & 1);
                    int r = wm * 32 + mi * 16 + (lane >> 2) + ((e >> 1) * 8);
                    sv[col * 129 + r] = acc[mi][ni][e];
                }
        __syncthreads();
        for (int i = tid; i < 128 * 32; i += 256) {
            int col = i >> 5, t4 = (i & 31) * 4;
            float v0 = sv[col * 129 + t4 + 0];
            float v1 = sv[col * 129 + t4 + 1];
            float v2 = sv[col * 129 + t4 + 2];
            float v3 = sv[col * 129 + t4 + 3];
            int hv = nsec / 64 + (col >> 6);
            int d = col & 63;
            int bhv = b * H_ + hv;
            size_t ob = ((size_t)bhv * D_ + d) * (size_t)N_ + t_base + t4;
            uint2 Hv, Lv;
            split2(v0, v1, Hv.x, Lv.x);
            split2(v2, v3, Hv.y, Lv.y);
            *(uint2*)(Vth + ob) = Hv;
            *(uint2*)(Vtl + ob) = Lv;
        }
    }
}

// ---------------------------------------------------------------------------
// Plain GEMM (projection)
// ---------------------------------------------------------------------------
__global__ __launch_bounds__(256, 2)
void tc_gemm(const __nv_bfloat16* __restrict__ Ah, const __nv_bfloat16* __restrict__ Al,
             const __nv_bfloat16* __restrict__ Bh, const __nv_bfloat16* __restrict__ Bl,
             const float* __restrict__ bias, float* __restrict__ C,
             int Ntot, int Ktot)
{
    extern __shared__ char smem[];
    uint32_t sbase = smem_u32(smem);
    int tid = threadIdx.x, lane = tid & 31, wid = tid >> 5;
    int wm = wid & 3, wn = wid >> 2;
    int m0 = blockIdx.y * 128, n0 = blockIdx.x * 128;

    float acc[2][8][4];
    #pragma unroll
    for (int mi = 0; mi < 2; mi++)
        #pragma unroll
        for (int ni = 0; ni < 8; ni++)
            #pragma unroll
            for (int e = 0; e < 4; e++) acc[mi][ni][e] = 0.f;

    gemm_mainloop(sbase, tid, lane, wm, wn, Ah, Al, Bh, Bl, m0, n0, Ktot, acc);

    #pragma unroll
    for (int mi = 0; mi < 2; mi++) {
        #pragma unroll
        for (int ni = 0; ni < 8; ni++) {
            int row = m0 + wm * 32 + mi * 16 + (lane >> 2);
            int col = n0 + wn * 64 + ni * 8 + (lane & 3) * 2;
            float2 bv = *(const float2*)&bias[col];
            float2 v0 = {acc[mi][ni][0] + bv.x, acc[mi][ni][1] + bv.y};
            float2 v1 = {acc[mi][ni][2] + bv.x, acc[mi][ni][3] + bv.y};
            *(float2*)&C[(size_t)row * Ntot + col] = v0;
            *(float2*)&C[(size_t)(row + 8) * Ntot + col] = v1;
        }
    }
}

// ---------------------------------------------------------------------------
// Tensor-core flash attention: 2-stage, occ 2, Q frags in regs,
// strength-reduced load addresses. Smem: Qh@0, Ql@16K, stages @32K/@64K.
// ---------------------------------------------------------------------------
__global__ __launch_bounds__(256, 2) void attn_mma(
    const __nv_bfloat16* __restrict__ Qh, const __nv_bfloat16* __restrict__ Ql,
    const __nv_bfloat16* __restrict__ Kh, const __nv_bfloat16* __restrict__ Kl,
    const __nv_bfloat16* __restrict__ Vth, const __nv_bfloat16* __restrict__ Vtl,
    __nv_bfloat16* __restrict__ Oh, __nv_bfloat16* __restrict__ Ol)
{
    extern __shared__ char smem[];
    uint32_t sb = smem_u32(smem);
    const uint32_t oQh = 0, oQl = 16384, oStage = 32768;

    int tid = threadIdx.x, lane = tid & 31, wq = tid >> 5;
    int bh = blockIdx.y;
    int q0 = blockIdx.x * 128;
    int b = bh / H_, h = bh % H_;

    const __nv_bfloat16* Qhb = Qh + ((size_t)bh * N_ + q0) * D_;
    const __nv_bfloat16* Qlb = Ql + ((size_t)bh * N_ + q0) * D_;
    const __nv_bfloat16* Khb = Kh + (size_t)bh * N_ * D_;
    const __nv_bfloat16* Klb = Kl + (size_t)bh * N_ * D_;
    const __nv_bfloat16* Vhb = Vth + (size_t)bh * D_ * N_;
    const __nv_bfloat16* Vlb = Vtl + (size_t)bh * D_ * N_;

    for (int u = tid; u < 2048; u += 256) {
        int split = u >> 10;
        int idx = u & 1023;
        int r = idx >> 3, chunk = idx & 7;
        uint32_t off = (uint32_t)(r * 128 + ((chunk ^ (r & 7)) * 16));
        const __nv_bfloat16* src = (split ? Qlb : Qhb) + (size_t)r * D_ + chunk * 8;
        CPA16(sb + (split ? oQl : oQh) + off, (const void*)src);
    }

    const char* lp[8];
    uint32_t ls[8];
    uint32_t ld[8];
    #pragma unroll
    for (int u = 0; u < 8; u++) {
        int uu = tid + u * 256;
        int part = uu >> 9;
        int idx = uu & 511;
        int r = idx >> 3, chunk = idx & 7;
        ls[u] = (uint32_t)part * 8192u + (uint32_t)(r * 128 + ((chunk ^ (r & 7)) * 16));
        const __nv_bfloat16* src;
        if (part == 0)      src = Khb + (size_t)r * D_ + chunk * 8;
        else if (part == 1) src = Klb + (size_t)r * D_ + chunk * 8;
        else if (part == 2) src = Vhb + (size_t)r * N_ + chunk * 8;
        else                src = Vlb + (size_t)r * N_ + chunk * 8;
        lp[u] = (const char*)src;
        ld[u] = (part < 2) ? (uint32_t)(64 * D_ * 2) : (uint32_t)(64 * 2);
    }
    auto load_stage = [&](int st) {
        uint32_t s0 = sb + oStage + (uint32_t)st * 32768u;
        #pragma unroll
        for (int u = 0; u < 8; u++) {
            CPA16(s0 + ls[u], lp[u]);
            lp[u] += ld[u];
        }
    };

    float o[8][4];
    #pragma unroll
    for (int i = 0; i < 8; i++)
        #pragma unroll
        for (int j = 0; j < 4; j++) o[i][j] = 0.f;
    float m0v = -1e30f, m1v = -1e30f, l0 = 0.f, l1 = 0.f;

    uint32_t qah[4][4], qal[4][4];

    load_stage(0); CP_COMMIT();
    load_stage(1); CP_COMMIT();

    for (int it = 0; it < 16; it++) {
        CP_WAIT1();
        __syncthreads();
        uint32_t sK = sb + oStage + (uint32_t)(it & 1) * 32768u;

        if (it == 0) {
            #pragma unroll
            for (int ks = 0; ks < 4; ks++) {
                int chunk = ks * 2 + (lane >> 4);
                int rq = wq * 16 + (lane & 15);
                uint32_t offq = (uint32_t)(rq * 128 + ((chunk ^ (rq & 7)) * 16));
                ldsm_x4(sb + oQh + offq, qah[ks][0], qah[ks][1], qah[ks][2], qah[ks][3]);
                ldsm_x4(sb + oQl + offq, qal[ks][0], qal[ks][1], qal[ks][2], qal[ks][3]);
            }
        }

        float c[8][4];
        #pragma unroll
        for (int i = 0; i < 8; i++)
            #pragma unroll
            for (int j = 0; j < 4; j++) c[i][j] = 0.f;

        #pragma unroll
        for (int ks = 0; ks < 4; ks++) {
            uint32_t bh_[8][2], bl_[8][2];
            #pragma unroll
            for (int p = 0; p < 4; p++) {
                int rk = p * 16 + (lane & 15);
                int chunk = ks * 2 + (lane >> 4);
                uint32_t offk = (uint32_t)(rk * 128 + ((chunk ^ (rk & 7)) * 16));
                uint32_t t0, t1, t2, t3;
                ldsm_x4(sK + offk, t0, t1, t2, t3);
                bh_[2*p][0] = t0; bh_[2*p][1] = t2; bh_[2*p+1][0] = t1; bh_[2*p+1][1] = t3;
                ldsm_x4(sK + 8192u + offk, t0, t1, t2, t3);
                bl_[2*p][0] = t0; bl_[2*p][1] = t2; bl_[2*p+1][0] = t1; bl_[2*p+1][1] = t3;
            }
            #pragma unroll
            for (int nt = 0; nt < 8; nt++) {
                mma_bf16(c[nt], qah[ks], bh_[nt]);
                mma_bf16(c[nt], qah[ks], bl_[nt]);
                mma_bf16(c[nt], qal[ks], bh_[nt]);
            }
        }

        // online softmax
        {
            float mt0 = -1e30f, mt1 = -1e30f;
            #pragma unroll
            for (int t = 0; t < 8; t++) {
                mt0 = fmaxf(mt0, fmaxf(c[t][0], c[t][1]));
                mt1 = fmaxf(mt1, fmaxf(c[t][2], c[t][3]));
            }
            mt0 = fmaxf(mt0, __shfl_xor_sync(0xffffffffu, mt0, 1));
            mt0 = fmaxf(mt0, __shfl_xor_sync(0xffffffffu, mt0, 2));
            mt1 = fmaxf(mt1, __shfl_xor_sync(0xffffffffu, mt1, 1));
            mt1 = fmaxf(mt1, __shfl_xor_sync(0xffffffffu, mt1, 2));
            float mn0 = fmaxf(m0v, mt0), mn1 = fmaxf(m1v, mt1);
            float f0 = __expf(m0v - mn0), f1 = __expf(m1v - mn1);
            m0v = mn0; m1v = mn1;
            float ps0 = 0.f, ps1 = 0.f;
            #pragma unroll
            for (int t = 0; t < 8; t++) {
                c[t][0] = __expf(c[t][0] - mn0); ps0 += c[t][0];
                c[t][1] = __expf(c[t][1] - mn0); ps0 += c[t][1];
                c[t][2] = __expf(c[t][2] - mn1); ps1 += c[t][2];
                c[t][3] = __expf(c[t][3] - mn1); ps1 += c[t][3];
            }
            ps0 += __shfl_xor_sync(0xffffffffu, ps0, 1);
            ps0 += __shfl_xor_sync(0xffffffffu, ps0, 2);
            ps1 += __shfl_xor_sync(0xffffffffu, ps1, 1);
            ps1 += __shfl_xor_sync(0xffffffffu, ps1, 2);
            l0 = l0 * f0 + ps0;
            l1 = l1 * f1 + ps1;
            #pragma unroll
            for (int t = 0; t < 8; t++) {
                o[t][0] *= f0; o[t][1] *= f0;
                o[t][2] *= f1; o[t][3] *= f1;
            }
        }

        // P fragments (hi/lo)
        uint32_t aph[4][4], apl[4][4];
        #pragma unroll
        for (int s = 0; s < 4; s++) {
            #pragma unroll
            for (int half = 0; half < 2; half++) {
                int t = 2 * s + half;
                split2(c[t][0], c[t][1], aph[s][half*2+0], apl[s][half*2+0]);
                split2(c[t][2], c[t][3], aph[s][half*2+1], apl[s][half*2+1]);
            }
        }

        // O += P V
        #pragma unroll
        for (int s = 0; s < 4; s++) {
            int chunk = s * 2 + (lane >> 4);
            uint32_t bh_[8][2], bl_[8][2];
            #pragma unroll
            for (int p = 0; p < 4; p++) {
                int rd = p * 16 + (lane & 15);
                uint32_t off = (uint32_t)(rd * 128 + ((chunk ^ (rd & 7)) * 16));
                uint32_t t0, t1, t2, t3;
                ldsm_x4(sK + 16384u + off, t0, t1, t2, t3);
                bh_[2*p][0] = t0; bh_[2*p][1] = t2; bh_[2*p+1][0] = t1; bh_[2*p+1][1] = t3;
                ldsm_x4(sK + 24576u + off, t0, t1, t2, t3);
                bl_[2*p][0] = t0; bl_[2*p][1] = t2; bl_[2*p+1][0] = t1; bl_[2*p+1][1] = t3;
            }
            #pragma unroll
            for (int nt = 0; nt < 8; nt++) {
                mma_bf16(o[nt], aph[s], bh_[nt]);
                mma_bf16(o[nt], aph[s], bl_[nt]);
                mma_bf16(o[nt], apl[s], bh_[nt]);
            }
        }

        __syncthreads();
        if (it + 2 < 16) load_stage(it & 1);
        CP_COMMIT();
    }

    // epilogue: normalize + hi/lo split
    float inv0 = 1.0f / l0, inv1 = 1.0f / l1;
    int r = lane >> 2;
    int row0 = q0 + wq * 16 + r;
    size_t base0 = ((size_t)(b * N_) + row0) * E_ + h * 64 + (lane & 3) * 2;
    size_t base1 = base0 + (size_t)8 * E_;
    #pragma unroll
    for (int t = 0; t < 8; t++) {
        uint32_t H, L;
        split2(o[t][0] * inv0, o[t][1] * inv0, H, L);
        *(uint32_t*)(Oh + base0 + t * 8) = H;
        *(uint32_t*)(Ol + base0 + t * 8) = L;
        split2(o[t][2] * inv1, o[t][3] * inv1, H, L);
        *(uint32_t*)(Oh + base1 + t * 8) = H;
        *(uint32_t*)(Ol + base1 + t * 8) = L;
    }
}

// ---------------------------------------------------------------------------
extern "C" void kernel_launch(void* const* d_in, const int* in_sizes, int n_in,
                              void* d_out, int out_size)
{
    (void)in_sizes; (void)n_in; (void)out_size;
    const float* x      = (const float*)d_in[0];
    const float* w_qkv  = (const float*)d_in[1];
    const float* b_qkv  = (const float*)d_in[2];
    const float* w_proj = (const float*)d_in[3];
    const float* b_proj = (const float*)d_in[4];
    float* out = (float*)d_out;

    __nv_bfloat16 *xh, *xl, *wqh, *wql, *wph, *wpl, *aoh, *aol;
    __nv_bfloat16 *qh2, *ql2, *kh2, *kl2, *vth, *vtl;
    cudaGetSymbolAddress((void**)&xh,  g_xh);
    cudaGetSymbolAddress((void**)&xl,  g_xl);
    cudaGetSymbolAddress((void**)&wqh, g_wqh);
    cudaGetSymbolAddress((void**)&wql, g_wql);
    cudaGetSymbolAddress((void**)&wph, g_wph);
    cudaGetSymbolAddress((void**)&wpl, g_wpl);
    cudaGetSymbolAddress((void**)&aoh, g_aoh);
    cudaGetSymbolAddress((void**)&aol, g_aol);
    cudaGetSymbolAddress((void**)&qh2, g_qh2);
    cudaGetSymbolAddress((void**)&ql2, g_ql2);
    cudaGetSymbolAddress((void**)&kh2, g_kh2);
    cudaGetSymbolAddress((void**)&kl2, g_kl2);
    cudaGetSymbolAddress((void**)&vth, g_vth);
    cudaGetSymbolAddress((void**)&vtl, g_vtl);

    // 66560 B: covers 64KB double-buffer AND the 66048 B V-transpose buffer.
    const int GEMM_SMEM = 66560;
    cudaFuncSetAttribute(tc_gemm_qkv, cudaFuncAttributeMaxDynamicSharedMemorySize, GEMM_SMEM);
    cudaFuncSetAttribute(tc_gemm, cudaFuncAttributeMaxDynamicSharedMemorySize, GEMM_SMEM);
    const int ATTN_SMEM = 3 * 32768;   // Q 32K + 2 stages
    cudaFuncSetAttribute(attn_mma, cudaFuncAttributeMaxDynamicSharedMemorySize, ATTN_SMEM);

    {
        int n4 = M_ * E_ / 4;
        convert_split<<<(n4 + 255) / 256, 256>>>((const float4*)x, (uint2*)xh, (uint2*)xl, n4);
    }
    {
        dim3 blk(32, 8);
        convert_w_t<<<dim3(3 * E_ / 32, E_ / 32), blk>>>(w_qkv, wqh, wql, E_, 3 * E_);
        convert_w_t<<<dim3(E_ / 32, E_ / 32), blk>>>(w_proj, wph, wpl, E_, E_);
    }
    {
        dim3 grid(3 * E_ / 128, M_ / 128);
        tc_gemm_qkv<<<grid, 256, GEMM_SMEM>>>(xh, xl, wqh, wql, b_qkv,
                                              qh2, ql2, kh2, kl2, vth, vtl);
    }
    {
        dim3 grid(N_ / 128, B_ * H_);
        attn_mma<<<grid, 256, ATTN_SMEM>>>(qh2, ql2, kh2, kl2, vth, vtl, aoh, aol);
    }
    {
        dim3 grid(E_ / 128, M_ / 128);
        tc_gemm<<<grid, 256, GEMM_SMEM>>>(aoh, aol, wph, wpl, b_proj, out, E_, E_);
    }
}

// round 9
// speedup vs baseline: 1.0485x; 1.0485x over previous
#include <cuda_runtime.h>
#include <cuda_bf16.h>
#include <math.h>
#include <stdint.h>

#define B_ 8
#define N_ 1024
#define E_ 768
#define H_ 12
#define D_ 64
#define M_ (B_*N_)   // 8192

// ---------------------------------------------------------------------------
// Scratch (__device__ globals; no allocations allowed)
// ---------------------------------------------------------------------------
__device__ __nv_bfloat16 g_xh[(size_t)M_ * E_];
__device__ __nv_bfloat16 g_xl[(size_t)M_ * E_];
__device__ __nv_bfloat16 g_wqh[(size_t)3*E_ * E_];
__device__ __nv_bfloat16 g_wql[(size_t)3*E_ * E_];
__device__ __nv_bfloat16 g_wph[(size_t)E_ * E_];
__device__ __nv_bfloat16 g_wpl[(size_t)E_ * E_];
__device__ __nv_bfloat16 g_aoh[(size_t)M_ * E_];
__device__ __nv_bfloat16 g_aol[(size_t)M_ * E_];
__device__ __nv_bfloat16 g_qh2[(size_t)B_*H_*N_*D_];
__device__ __nv_bfloat16 g_ql2[(size_t)B_*H_*N_*D_];
__device__ __nv_bfloat16 g_kh2[(size_t)B_*H_*N_*D_];
__device__ __nv_bfloat16 g_kl2[(size_t)B_*H_*N_*D_];
__device__ __nv_bfloat16 g_vth[(size_t)B_*H_*D_*N_];
__device__ __nv_bfloat16 g_vtl[(size_t)B_*H_*D_*N_];

// ---------------------------------------------------------------------------
// PTX helpers
// ---------------------------------------------------------------------------
__device__ __forceinline__ uint32_t smem_u32(const void* p) {
    uint32_t a;
    asm("{ .reg .u64 t; cvta.to.shared.u64 t, %1; cvt.u32.u64 %0, t; }" : "=r"(a) : "l"(p));
    return a;
}
#define CPA16(dst, src) \
    asm volatile("cp.async.cg.shared.global [%0], [%1], 16;" :: "r"(dst), "l"(src) : "memory")
#define CP_COMMIT() asm volatile("cp.async.commit_group;" ::: "memory")
#define CP_WAIT1()  asm volatile("cp.async.wait_group 1;" ::: "memory")

__device__ __forceinline__ void ldsm_x4(uint32_t addr, uint32_t& r0, uint32_t& r1,
                                        uint32_t& r2, uint32_t& r3) {
    asm volatile("ldmatrix.sync.aligned.m8n8.x4.shared.b16 {%0,%1,%2,%3}, [%4];"
                 : "=r"(r0), "=r"(r1), "=r"(r2), "=r"(r3) : "r"(addr));
}
__device__ __forceinline__ void mma_bf16(float* c, const uint32_t* a, const uint32_t* b) {
    asm volatile("mma.sync.aligned.m16n8k16.row.col.f32.bf16.bf16.f32 "
        "{%0,%1,%2,%3}, {%4,%5,%6,%7}, {%8,%9}, {%0,%1,%2,%3};"
        : "+f"(c[0]), "+f"(c[1]), "+f"(c[2]), "+f"(c[3])
        : "r"(a[0]), "r"(a[1]), "r"(a[2]), "r"(a[3]), "r"(b[0]), "r"(b[1]));
}
__device__ __forceinline__ uint32_t pack_bf16x2(float lo, float hi) {
    __nv_bfloat162 t = __floats2bfloat162_rn(lo, hi);
    return *(uint32_t*)&t;
}
__device__ __forceinline__ void split2(float v0, float v1, uint32_t& hi, uint32_t& lo) {
    __nv_bfloat16 h0 = __float2bfloat16(v0), h1 = __float2bfloat16(v1);
    hi = (uint32_t)__bfloat16_as_ushort(h0) | ((uint32_t)__bfloat16_as_ushort(h1) << 16);
    lo = pack_bf16x2(v0 - __bfloat162float(h0), v1 - __bfloat162float(h1));
}

// ---------------------------------------------------------------------------
// convert kernels
// ---------------------------------------------------------------------------
__global__ void convert_split(const float4* __restrict__ in,
                              uint2* __restrict__ hi, uint2* __restrict__ lo, int n4)
{
    int i = blockIdx.x * blockDim.x + threadIdx.x;
    if (i >= n4) return;
    float4 v = in[i];
    uint2 H, L;
    split2(v.x, v.y, H.x, L.x);
    split2(v.z, v.w, H.y, L.y);
    hi[i] = H;
    lo[i] = L;
}

__global__ void convert_w_t(const float* __restrict__ W,
                            __nv_bfloat16* __restrict__ Th, __nv_bfloat16* __restrict__ Tl,
                            int K, int N)
{
    __shared__ float tile[32][33];
    int n0 = blockIdx.x * 32, k0 = blockIdx.y * 32;
    int tx = threadIdx.x, ty = threadIdx.y;
    for (int i = ty; i < 32; i += 8)
        tile[i][tx] = W[(size_t)(k0 + i) * N + n0 + tx];
    __syncthreads();
    for (int i = ty; i < 32; i += 8) {
        float v = tile[tx][i];
        __nv_bfloat16 h = __float2bfloat16(v);
        Th[(size_t)(n0 + i) * K + k0 + tx] = h;
        Tl[(size_t)(n0 + i) * K + k0 + tx] = __float2bfloat16(v - __bfloat162float(h));
    }
}

// ---------------------------------------------------------------------------
// GEMM mainloop, 4 warps (128 threads), warp tile 64x64, CTA tile 128x128.
// Per K-chunk per warp: 32 LDSM, 192 MMAs (6 MMA/LDSM). 2-stage pipeline.
// Smem per stage 32KB: Ah@0, Al@8K, Bh@16K, Bl@24K.
// ---------------------------------------------------------------------------
__device__ __forceinline__ void gemm_mainloop4(
    uint32_t sbase, int tid, int lane, int wm, int wn,
    const __nv_bfloat16* __restrict__ Ah, const __nv_bfloat16* __restrict__ Al,
    const __nv_bfloat16* __restrict__ Bh, const __nv_bfloat16* __restrict__ Bl,
    int m0, int n0, int Ktot, float (&acc)[4][8][4])
{
    const int NCH = Ktot / 32;

    auto load_stage = [&](int ch, int st) {
        uint32_t sb = sbase + (uint32_t)st * 32768u;
        int kb = ch * 32;
        #pragma unroll
        for (int u = 0; u < 4; u++) {
            int idx = tid + u * 128;          // 0..511
            int row = idx >> 2, chunk = idx & 3;
            uint32_t soff = (uint32_t)(row * 64 + ((chunk ^ (row & 3)) * 16));
            size_t ga = (size_t)(m0 + row) * Ktot + kb + chunk * 8;
            size_t gb = (size_t)(n0 + row) * Ktot + kb + chunk * 8;
            CPA16(sb +          soff, (const void*)(Ah + ga));
            CPA16(sb +  8192u + soff, (const void*)(Al + ga));
            CPA16(sb + 16384u + soff, (const void*)(Bh + gb));
            CPA16(sb + 24576u + soff, (const void*)(Bl + gb));
        }
    };

    auto compute_stage = [&](int st) {
        uint32_t sA = sbase + (uint32_t)st * 32768u;
        #pragma unroll
        for (int ks = 0; ks < 2; ks++) {
            int c2 = ks * 2 + (lane >> 4);
            uint32_t ah[4][4], al[4][4];
            #pragma unroll
            for (int mi = 0; mi < 4; mi++) {
                int r = wm * 64 + mi * 16 + (lane & 15);
                uint32_t off = (uint32_t)(r * 64 + ((c2 ^ (r & 3)) * 16));
                ldsm_x4(sA + off, ah[mi][0], ah[mi][1], ah[mi][2], ah[mi][3]);
                ldsm_x4(sA + 8192u + off, al[mi][0], al[mi][1], al[mi][2], al[mi][3]);
            }
            #pragma unroll
            for (int p = 0; p < 4; p++) {
                int r = wn * 64 + p * 16 + (lane & 15);
                uint32_t off = (uint32_t)(r * 64 + ((c2 ^ (r & 3)) * 16));
                uint32_t t0, t1, t2, t3;
                uint32_t bh0[2], bh1[2], bl0[2], bl1[2];
                ldsm_x4(sA + 16384u + off, t0, t1, t2, t3);
                bh0[0] = t0; bh0[1] = t2; bh1[0] = t1; bh1[1] = t3;
                ldsm_x4(sA + 24576u + off, t0, t1, t2, t3);
                bl0[0] = t0; bl0[1] = t2; bl1[0] = t1; bl1[1] = t3;
                #pragma unroll
                for (int mi = 0; mi < 4; mi++) {
                    mma_bf16(acc[mi][2*p],   ah[mi], bh0);
                    mma_bf16(acc[mi][2*p+1], ah[mi], bh1);
                    mma_bf16(acc[mi][2*p],   ah[mi], bl0);
                    mma_bf16(acc[mi][2*p+1], ah[mi], bl1);
                    mma_bf16(acc[mi][2*p],   al[mi], bh0);
                    mma_bf16(acc[mi][2*p+1], al[mi], bh1);
                }
            }
        }
    };

    load_stage(0, 0); CP_COMMIT();
    load_stage(1, 1); CP_COMMIT();

    for (int ch = 0; ch < NCH; ch++) {
        CP_WAIT1();
        __syncthreads();
        compute_stage(ch & 1);
        __syncthreads();
        if (ch + 2 < NCH) load_stage(ch + 2, ch & 1);
        CP_COMMIT();
    }
}

// ---------------------------------------------------------------------------
// Fused QKV GEMM: bias + RoPE + hi/lo split + V-transpose epilogue.
// 128 threads. V epilogue needs 66048 B smem -> GEMM_SMEM = 66560.
// ---------------------------------------------------------------------------
__global__ __launch_bounds__(128, 2)
void tc_gemm_qkv(const __nv_bfloat16* __restrict__ Ah, const __nv_bfloat16* __restrict__ Al,
                 const __nv_bfloat16* __restrict__ Bh, const __nv_bfloat16* __restrict__ Bl,
                 const float* __restrict__ bias,
                 __nv_bfloat16* __restrict__ Qh, __nv_bfloat16* __restrict__ Ql,
                 __nv_bfloat16* __restrict__ Kh, __nv_bfloat16* __restrict__ Kl,
                 __nv_bfloat16* __restrict__ Vth, __nv_bfloat16* __restrict__ Vtl)
{
    extern __shared__ char smem[];
    uint32_t sbase = smem_u32(smem);
    int tid = threadIdx.x, lane = tid & 31, wid = tid >> 5;
    int wm = wid & 1, wn = wid >> 1;
    int m0 = blockIdx.y * 128, n0 = blockIdx.x * 128;

    float acc[4][8][4];
    #pragma unroll
    for (int mi = 0; mi < 4; mi++)
        #pragma unroll
        for (int ni = 0; ni < 8; ni++)
            #pragma unroll
            for (int e = 0; e < 4; e++) acc[mi][ni][e] = 0.f;

    gemm_mainloop4(sbase, tid, lane, wm, wn, Ah, Al, Bh, Bl, m0, n0, E_, acc);
    __syncthreads();   // V branch reuses smem

    #pragma unroll
    for (int ni = 0; ni < 8; ni++) {
        int col = n0 + wn * 64 + ni * 8 + (lane & 3) * 2;
        float2 bv = *(const float2*)&bias[col];
        #pragma unroll
        for (int mi = 0; mi < 4; mi++) {
            acc[mi][ni][0] += bv.x; acc[mi][ni][1] += bv.y;
            acc[mi][ni][2] += bv.x; acc[mi][ni][3] += bv.y;
        }
    }

    int sec = n0 / 768;
    int nsec = n0 - sec * 768;
    int b = m0 >> 10;
    int t_base = m0 & 1023;

    if (sec < 2) {
        int h = nsec / 64 + wn;
        int bh = b * H_ + h;
        float cs[8], sn[8];
        #pragma unroll
        for (int u = 0; u < 8; u++) {
            int d2 = (u >> 1) * 8 + (lane & 3) * 2 + (u & 1);
            float f = (float)h * exp2f(-(float)d2 * (13.287712379549449f / 32.0f));
            sincosf(f, &sn[u], &cs[u]);
        }
        __nv_bfloat16* Oh = (sec == 0) ? Qh : Kh;
        __nv_bfloat16* Ol = (sec == 0) ? Ql : Kl;
        const float scale = (sec == 0) ? 0.125f : 1.0f;

        #pragma unroll
        for (int mi = 0; mi < 4; mi++) {
            int rbase = wm * 64 + mi * 16 + (lane >> 2);
            #pragma unroll
            for (int eh = 0; eh < 2; eh++) {
                int t = t_base + rbase + eh * 8;
                size_t rowoff = ((size_t)bh * N_ + t) * (size_t)D_;
                #pragma unroll
                for (int ni = 0; ni < 4; ni++) {
                    float a0 = acc[mi][ni][eh*2+0], b0 = acc[mi][ni+4][eh*2+0];
                    float a1 = acc[mi][ni][eh*2+1], b1 = acc[mi][ni+4][eh*2+1];
                    int u0 = ni * 2, u1 = u0 + 1;
                    float lo0 = (a0 * cs[u0] - b0 * sn[u0]) * scale;
                    float hi0 = (b0 * cs[u0] + a0 * sn[u0]) * scale;
                    float lo1 = (a1 * cs[u1] - b1 * sn[u1]) * scale;
                    float hi1 = (b1 * cs[u1] + a1 * sn[u1]) * scale;
                    int d0 = ni * 8 + (lane & 3) * 2;
                    uint32_t H, L;
                    split2(lo0, lo1, H, L);
                    *(uint32_t*)(Oh + rowoff + d0) = H;
                    *(uint32_t*)(Ol + rowoff + d0) = L;
                    split2(hi0, hi1, H, L);
                    *(uint32_t*)(Oh + rowoff + d0 + 32) = H;
                    *(uint32_t*)(Ol + rowoff + d0 + 32) = L;
                }
            }
        }
    } else {
        float* sv = (float*)smem;
        #pragma unroll
        for (int mi = 0; mi < 4; mi++)
            #pragma unroll
            for (int ni = 0; ni < 8; ni++)
                #pragma unroll
                for (int e = 0; e < 4; e++) {
                    int col = wn * 64 + ni * 8 + (lane & 3) * 2 + (e & 1);
                    int r = wm * 64 + mi * 16 + (lane >> 2) + ((e >> 1) * 8);
                    sv[col * 129 + r] = acc[mi][ni][e];
                }
        __syncthreads();
        for (int i = tid; i < 128 * 32; i += 128) {
            int col = i >> 5, t4 = (i & 31) * 4;
            float v0 = sv[col * 129 + t4 + 0];
            float v1 = sv[col * 129 + t4 + 1];
            float v2 = sv[col * 129 + t4 + 2];
            float v3 = sv[col * 129 + t4 + 3];
            int hv = nsec / 64 + (col >> 6);
            int d = col & 63;
            int bhv = b * H_ + hv;
            size_t ob = ((size_t)bhv * D_ + d) * (size_t)N_ + t_base + t4;
            uint2 Hv, Lv;
            split2(v0, v1, Hv.x, Lv.x);
            split2(v2, v3, Hv.y, Lv.y);
            *(uint2*)(Vth + ob) = Hv;
            *(uint2*)(Vtl + ob) = Lv;
        }
    }
}

// ---------------------------------------------------------------------------
// Plain GEMM (projection), 128 threads, warp tile 64x64.
// ---------------------------------------------------------------------------
__global__ __launch_bounds__(128, 2)
void tc_gemm(const __nv_bfloat16* __restrict__ Ah, const __nv_bfloat16* __restrict__ Al,
             const __nv_bfloat16* __restrict__ Bh, const __nv_bfloat16* __restrict__ Bl,
             const float* __restrict__ bias, float* __restrict__ C,
             int Ntot, int Ktot)
{
    extern __shared__ char smem[];
    uint32_t sbase = smem_u32(smem);
    int tid = threadIdx.x, lane = tid & 31, wid = tid >> 5;
    int wm = wid & 1, wn = wid >> 1;
    int m0 = blockIdx.y * 128, n0 = blockIdx.x * 128;

    float acc[4][8][4];
    #pragma unroll
    for (int mi = 0; mi < 4; mi++)
        #pragma unroll
        for (int ni = 0; ni < 8; ni++)
            #pragma unroll
            for (int e = 0; e < 4; e++) acc[mi][ni][e] = 0.f;

    gemm_mainloop4(sbase, tid, lane, wm, wn, Ah, Al, Bh, Bl, m0, n0, Ktot, acc);

    #pragma unroll
    for (int mi = 0; mi < 4; mi++) {
        #pragma unroll
        for (int ni = 0; ni < 8; ni++) {
            int row = m0 + wm * 64 + mi * 16 + (lane >> 2);
            int col = n0 + wn * 64 + ni * 8 + (lane & 3) * 2;
            float2 bv = *(const float2*)&bias[col];
            float2 v0 = {acc[mi][ni][0] + bv.x, acc[mi][ni][1] + bv.y};
            float2 v1 = {acc[mi][ni][2] + bv.x, acc[mi][ni][3] + bv.y};
            *(float2*)&C[(size_t)row * Ntot + col] = v0;
            *(float2*)&C[(size_t)(row + 8) * Ntot + col] = v1;
        }
    }
}

// ---------------------------------------------------------------------------
// Tensor-core flash attention — exact R5 version (best measured build).
// ---------------------------------------------------------------------------
__global__ __launch_bounds__(256, 2) void attn_mma(
    const __nv_bfloat16* __restrict__ Qh, const __nv_bfloat16* __restrict__ Ql,
    const __nv_bfloat16* __restrict__ Kh, const __nv_bfloat16* __restrict__ Kl,
    const __nv_bfloat16* __restrict__ Vth, const __nv_bfloat16* __restrict__ Vtl,
    __nv_bfloat16* __restrict__ Oh, __nv_bfloat16* __restrict__ Ol)
{
    extern __shared__ char smem[];
    uint32_t sb = smem_u32(smem);
    const uint32_t oQh = 0, oQl = 16384, oStage = 32768;

    int tid = threadIdx.x, lane = tid & 31, wq = tid >> 5;
    int bh = blockIdx.y;
    int q0 = blockIdx.x * 128;
    int b = bh / H_, h = bh % H_;

    const __nv_bfloat16* Qhb = Qh + ((size_t)bh * N_ + q0) * D_;
    const __nv_bfloat16* Qlb = Ql + ((size_t)bh * N_ + q0) * D_;
    const __nv_bfloat16* Khb = Kh + (size_t)bh * N_ * D_;
    const __nv_bfloat16* Klb = Kl + (size_t)bh * N_ * D_;
    const __nv_bfloat16* Vhb = Vth + (size_t)bh * D_ * N_;
    const __nv_bfloat16* Vlb = Vtl + (size_t)bh * D_ * N_;

    for (int u = tid; u < 2048; u += 256) {
        int split = u >> 10;
        int idx = u & 1023;
        int r = idx >> 3, chunk = idx & 7;
        uint32_t off = (uint32_t)(r * 128 + ((chunk ^ (r & 7)) * 16));
        const __nv_bfloat16* src = (split ? Qlb : Qhb) + (size_t)r * D_ + chunk * 8;
        CPA16(sb + (split ? oQl : oQh) + off, (const void*)src);
    }

    auto load_stage = [&](int it, int st) {
        int jt = it * 64;
        uint32_t s0 = sb + oStage + (uint32_t)st * 32768u;
        for (int u = tid; u < 2048; u += 256) {
            int part = u >> 9;
            int idx = u & 511;
            int r = idx >> 3, chunk = idx & 7;
            uint32_t off = (uint32_t)(r * 128 + ((chunk ^ (r & 7)) * 16));
            const __nv_bfloat16* src;
            if (part == 0)      src = Khb + (size_t)(jt + r) * D_ + chunk * 8;
            else if (part == 1) src = Klb + (size_t)(jt + r) * D_ + chunk * 8;
            else if (part == 2) src = Vhb + (size_t)r * N_ + jt + chunk * 8;
            else                src = Vlb + (size_t)r * N_ + jt + chunk * 8;
            CPA16(s0 + (uint32_t)part * 8192u + off, (const void*)src);
        }
    };

    float o[8][4];
    #pragma unroll
    for (int i = 0; i < 8; i++)
        #pragma unroll
        for (int j = 0; j < 4; j++) o[i][j] = 0.f;
    float m0v = -1e30f, m1v = -1e30f, l0 = 0.f, l1 = 0.f;

    load_stage(0, 0); CP_COMMIT();
    load_stage(1, 1); CP_COMMIT();

    for (int it = 0; it < 16; it++) {
        CP_WAIT1();
        __syncthreads();
        uint32_t sK = sb + oStage + (uint32_t)(it & 1) * 32768u;

        float c[8][4];
        #pragma unroll
        for (int i = 0; i < 8; i++)
            #pragma unroll
            for (int j = 0; j < 4; j++) c[i][j] = 0.f;

        #pragma unroll
        for (int ks = 0; ks < 4; ks++) {
            int chunk = ks * 2 + (lane >> 4);
            int rq = wq * 16 + (lane & 15);
            uint32_t offq = (uint32_t)(rq * 128 + ((chunk ^ (rq & 7)) * 16));
            uint32_t ah[4], al[4];
            ldsm_x4(sb + oQh + offq, ah[0], ah[1], ah[2], ah[3]);
            ldsm_x4(sb + oQl + offq, al[0], al[1], al[2], al[3]);
            uint32_t bh_[8][2], bl_[8][2];
            #pragma unroll
            for (int p = 0; p < 4; p++) {
                int rk = p * 16 + (lane & 15);
                uint32_t offk = (uint32_t)(rk * 128 + ((chunk ^ (rk & 7)) * 16));
                uint32_t t0, t1, t2, t3;
                ldsm_x4(sK + offk, t0, t1, t2, t3);
                bh_[2*p][0] = t0; bh_[2*p][1] = t2; bh_[2*p+1][0] = t1; bh_[2*p+1][1] = t3;
                ldsm_x4(sK + 8192u + offk, t0, t1, t2, t3);
                bl_[2*p][0] = t0; bl_[2*p][1] = t2; bl_[2*p+1][0] = t1; bl_[2*p+1][1] = t3;
            }
            #pragma unroll
            for (int nt = 0; nt < 8; nt++) mma_bf16(c[nt], ah, bh_[nt]);
            #pragma unroll
            for (int nt = 0; nt < 8; nt++) mma_bf16(c[nt], ah, bl_[nt]);
            #pragma unroll
            for (int nt = 0; nt < 8; nt++) mma_bf16(c[nt], al, bh_[nt]);
        }

        // online softmax
        {
            float mt0 = -1e30f, mt1 = -1e30f;
            #pragma unroll
            for (int t = 0; t < 8; t++) {
                mt0 = fmaxf(mt0, fmaxf(c[t][0], c[t][1]));
                mt1 = fmaxf(mt1, fmaxf(c[t][2], c[t][3]));
            }
            mt0 = fmaxf(mt0, __shfl_xor_sync(0xffffffffu, mt0, 1));
            mt0 = fmaxf(mt0, __shfl_xor_sync(0xffffffffu, mt0, 2));
            mt1 = fmaxf(mt1, __shfl_xor_sync(0xffffffffu, mt1, 1));
            mt1 = fmaxf(mt1, __shfl_xor_sync(0xffffffffu, mt1, 2));
            float mn0 = fmaxf(m0v, mt0), mn1 = fmaxf(m1v, mt1);
            float f0 = __expf(m0v - mn0), f1 = __expf(m1v - mn1);
            m0v = mn0; m1v = mn1;
            float ps0 = 0.f, ps1 = 0.f;
            #pragma unroll
            for (int t = 0; t < 8; t++) {
                c[t][0] = __expf(c[t][0] - mn0); ps0 += c[t][0];
                c[t][1] = __expf(c[t][1] - mn0); ps0 += c[t][1];
                c[t][2] = __expf(c[t][2] - mn1); ps1 += c[t][2];
                c[t][3] = __expf(c[t][3] - mn1); ps1 += c[t][3];
            }
            ps0 += __shfl_xor_sync(0xffffffffu, ps0, 1);
            ps0 += __shfl_xor_sync(0xffffffffu, ps0, 2);
            ps1 += __shfl_xor_sync(0xffffffffu, ps1, 1);
            ps1 += __shfl_xor_sync(0xffffffffu, ps1, 2);
            l0 = l0 * f0 + ps0;
            l1 = l1 * f1 + ps1;
            #pragma unroll
            for (int t = 0; t < 8; t++) {
                o[t][0] *= f0; o[t][1] *= f0;
                o[t][2] *= f1; o[t][3] *= f1;
            }
        }

        // P fragments (hi/lo)
        uint32_t aph[4][4], apl[4][4];
        #pragma unroll
        for (int s = 0; s < 4; s++) {
            #pragma unroll
            for (int half = 0; half < 2; half++) {
                int t = 2 * s + half;
                split2(c[t][0], c[t][1], aph[s][half*2+0], apl[s][half*2+0]);
                split2(c[t][2], c[t][3], aph[s][half*2+1], apl[s][half*2+1]);
            }
        }

        // O += P V
        #pragma unroll
        for (int s = 0; s < 4; s++) {
            int chunk = s * 2 + (lane >> 4);
            uint32_t bh_[8][2], bl_[8][2];
            #pragma unroll
            for (int p = 0; p < 4; p++) {
                int rd = p * 16 + (lane & 15);
                uint32_t off = (uint32_t)(rd * 128 + ((chunk ^ (rd & 7)) * 16));
                uint32_t t0, t1, t2, t3;
                ldsm_x4(sK + 16384u + off, t0, t1, t2, t3);
                bh_[2*p][0] = t0; bh_[2*p][1] = t2; bh_[2*p+1][0] = t1; bh_[2*p+1][1] = t3;
                ldsm_x4(sK + 24576u + off, t0, t1, t2, t3);
                bl_[2*p][0] = t0; bl_[2*p][1] = t2; bl_[2*p+1][0] = t1; bl_[2*p+1][1] = t3;
            }
            #pragma unroll
            for (int nt = 0; nt < 8; nt++) mma_bf16(o[nt], aph[s], bh_[nt]);
            #pragma unroll
            for (int nt = 0; nt < 8; nt++) mma_bf16(o[nt], aph[s], bl_[nt]);
            #pragma unroll
            for (int nt = 0; nt < 8; nt++) mma_bf16(o[nt], apl[s], bh_[nt]);
        }

        __syncthreads();
        if (it + 2 < 16) load_stage(it + 2, it & 1);
        CP_COMMIT();
    }

    // epilogue: normalize + hi/lo split
    float inv0 = 1.0f / l0, inv1 = 1.0f / l1;
    int r = lane >> 2;
    int row0 = q0 + wq * 16 + r;
    size_t base0 = ((size_t)(b * N_) + row0) * E_ + h * 64 + (lane & 3) * 2;
    size_t base1 = base0 + (size_t)8 * E_;
    #pragma unroll
    for (int t = 0; t < 8; t++) {
        uint32_t H, L;
        split2(o[t][0] * inv0, o[t][1] * inv0, H, L);
        *(uint32_t*)(Oh + base0 + t * 8) = H;
        *(uint32_t*)(Ol + base0 + t * 8) = L;
        split2(o[t][2] * inv1, o[t][3] * inv1, H, L);
        *(uint32_t*)(Oh + base1 + t * 8) = H;
        *(uint32_t*)(Ol + base1 + t * 8) = L;
    }
}

// ---------------------------------------------------------------------------
extern "C" void kernel_launch(void* const* d_in, const int* in_sizes, int n_in,
                              void* d_out, int out_size)
{
    (void)in_sizes; (void)n_in; (void)out_size;
    const float* x      = (const float*)d_in[0];
    const float* w_qkv  = (const float*)d_in[1];
    const float* b_qkv  = (const float*)d_in[2];
    const float* w_proj = (const float*)d_in[3];
    const float* b_proj = (const float*)d_in[4];
    float* out = (float*)d_out;

    __nv_bfloat16 *xh, *xl, *wqh, *wql, *wph, *wpl, *aoh, *aol;
    __nv_bfloat16 *qh2, *ql2, *kh2, *kl2, *vth, *vtl;
    cudaGetSymbolAddress((void**)&xh,  g_xh);
    cudaGetSymbolAddress((void**)&xl,  g_xl);
    cudaGetSymbolAddress((void**)&wqh, g_wqh);
    cudaGetSymbolAddress((void**)&wql, g_wql);
    cudaGetSymbolAddress((void**)&wph, g_wph);
    cudaGetSymbolAddress((void**)&wpl, g_wpl);
    cudaGetSymbolAddress((void**)&aoh, g_aoh);
    cudaGetSymbolAddress((void**)&aol, g_aol);
    cudaGetSymbolAddress((void**)&qh2, g_qh2);
    cudaGetSymbolAddress((void**)&ql2, g_ql2);
    cudaGetSymbolAddress((void**)&kh2, g_kh2);
    cudaGetSymbolAddress((void**)&kl2, g_kl2);
    cudaGetSymbolAddress((void**)&vth, g_vth);
    cudaGetSymbolAddress((void**)&vtl, g_vtl);

    // 66560 B: covers 64KB double-buffer AND the 66048 B V-transpose buffer.
    const int GEMM_SMEM = 66560;
    cudaFuncSetAttribute(tc_gemm_qkv, cudaFuncAttributeMaxDynamicSharedMemorySize, GEMM_SMEM);
    cudaFuncSetAttribute(tc_gemm, cudaFuncAttributeMaxDynamicSharedMemorySize, GEMM_SMEM);
    const int ATTN_SMEM = 3 * 32768;   // Q 32K + 2 stages
    cudaFuncSetAttribute(attn_mma, cudaFuncAttributeMaxDynamicSharedMemorySize, ATTN_SMEM);

    {
        int n4 = M_ * E_ / 4;
        convert_split<<<(n4 + 255) / 256, 256>>>((const float4*)x, (uint2*)xh, (uint2*)xl, n4);
    }
    {
        dim3 blk(32, 8);
        convert_w_t<<<dim3(3 * E_ / 32, E_ / 32), blk>>>(w_qkv, wqh, wql, E_, 3 * E_);
        convert_w_t<<<dim3(E_ / 32, E_ / 32), blk>>>(w_proj, wph, wpl, E_, E_);
    }
    {
        dim3 grid(3 * E_ / 128, M_ / 128);
        tc_gemm_qkv<<<grid, 128, GEMM_SMEM>>>(xh, xl, wqh, wql, b_qkv,
                                              qh2, ql2, kh2, kl2, vth, vtl);
    }
    {
        dim3 grid(N_ / 128, B_ * H_);
        attn_mma<<<grid, 256, ATTN_SMEM>>>(qh2, ql2, kh2, kl2, vth, vtl, aoh, aol);
    }
    {
        dim3 grid(E_ / 128, M_ / 128);
        tc_gemm<<<grid, 128, GEMM_SMEM>>>(aoh, aol, wph, wpl, b_proj, out, E_, E_);
    }
}

// round 10
// speedup vs baseline: 1.4723x; 1.4042x over previous
#include <cuda_runtime.h>
#include <cuda_fp16.h>
#include <math.h>
#include <stdint.h>

#define B_ 8
#define N_ 1024
#define E_ 768
#define H_ 12
#define D_ 64
#define M_ (B_*N_)   // 8192

// ---------------------------------------------------------------------------
// Scratch (__device__ globals; no allocations allowed)
// ---------------------------------------------------------------------------
__device__ __half g_xh[(size_t)M_ * E_];          // x split (A-side)
__device__ __half g_xl[(size_t)M_ * E_];
__device__ __half g_wq[(size_t)3*E_ * E_];        // w_qkv^T single fp16
__device__ __half g_wp[(size_t)E_ * E_];          // w_proj^T single fp16
__device__ __half g_aoh[(size_t)M_ * E_];         // attention out split (A-side)
__device__ __half g_aol[(size_t)M_ * E_];
__device__ __half g_qh2[(size_t)B_*H_*N_*D_];     // Q split (A-side of S)
__device__ __half g_ql2[(size_t)B_*H_*N_*D_];
__device__ __half g_k2[(size_t)B_*H_*N_*D_];      // K single fp16
__device__ __half g_vt[(size_t)B_*H_*D_*N_];      // V^T single fp16

// ---------------------------------------------------------------------------
// PTX helpers
// ---------------------------------------------------------------------------
__device__ __forceinline__ uint32_t smem_u32(const void* p) {
    uint32_t a;
    asm("{ .reg .u64 t; cvta.to.shared.u64 t, %1; cvt.u32.u64 %0, t; }" : "=r"(a) : "l"(p));
    return a;
}
#define CPA16(dst, src) \
    asm volatile("cp.async.cg.shared.global [%0], [%1], 16;" :: "r"(dst), "l"(src) : "memory")
#define CP_COMMIT() asm volatile("cp.async.commit_group;" ::: "memory")
#define CP_WAIT1()  asm volatile("cp.async.wait_group 1;" ::: "memory")

__device__ __forceinline__ void ldsm_x4(uint32_t addr, uint32_t& r0, uint32_t& r1,
                                        uint32_t& r2, uint32_t& r3) {
    asm volatile("ldmatrix.sync.aligned.m8n8.x4.shared.b16 {%0,%1,%2,%3}, [%4];"
                 : "=r"(r0), "=r"(r1), "=r"(r2), "=r"(r3) : "r"(addr));
}
__device__ __forceinline__ void mma_f16(float* c, const uint32_t* a, const uint32_t* b) {
    asm volatile("mma.sync.aligned.m16n8k16.row.col.f32.f16.f16.f32 "
        "{%0,%1,%2,%3}, {%4,%5,%6,%7}, {%8,%9}, {%0,%1,%2,%3};"
        : "+f"(c[0]), "+f"(c[1]), "+f"(c[2]), "+f"(c[3])
        : "r"(a[0]), "r"(a[1]), "r"(a[2]), "r"(a[3]), "r"(b[0]), "r"(b[1]));
}
__device__ __forceinline__ uint32_t packh2(float a, float b) {
    __half2 t = __floats2half2_rn(a, b);
    return *(uint32_t*)&t;
}
// split two fp32 into exact fp16 hi-pair + lo-pair
__device__ __forceinline__ void split2h(float v0, float v1, uint32_t& hi, uint32_t& lo) {
    __half h0 = __float2half_rn(v0), h1 = __float2half_rn(v1);
    hi = (uint32_t)__half_as_ushort(h0) | ((uint32_t)__half_as_ushort(h1) << 16);
    lo = packh2(v0 - __half2float(h0), v1 - __half2float(h1));
}

// ---------------------------------------------------------------------------
// convert kernels
// ---------------------------------------------------------------------------
__global__ void convert_split(const float4* __restrict__ in,
                              uint2* __restrict__ hi, uint2* __restrict__ lo, int n4)
{
    int i = blockIdx.x * blockDim.x + threadIdx.x;
    if (i >= n4) return;
    float4 v = in[i];
    uint2 H, L;
    split2h(v.x, v.y, H.x, L.x);
    split2h(v.z, v.w, H.y, L.y);
    hi[i] = H;
    lo[i] = L;
}

// W [K,N] fp32 -> W^T [N,K] single fp16
__global__ void convert_w_t(const float* __restrict__ W,
                            __half* __restrict__ T, int K, int N)
{
    __shared__ float tile[32][33];
    int n0 = blockIdx.x * 32, k0 = blockIdx.y * 32;
    int tx = threadIdx.x, ty = threadIdx.y;
    for (int i = ty; i < 32; i += 8)
        tile[i][tx] = W[(size_t)(k0 + i) * N + n0 + tx];
    __syncthreads();
    for (int i = ty; i < 32; i += 8)
        T[(size_t)(n0 + i) * K + k0 + tx] = __float2half_rn(tile[tx][i]);
}

// ---------------------------------------------------------------------------
// GEMM mainloop (R4 schedule: 2-stage, two syncs). A split (ah+al), B single.
// Smem per stage 24KB: Ah@0, Al@8K, B@16K. 8 warps, warp tile 32x64.
// Per (mi,ni) per ks: 2 MMAs (ah*b, al*b).
// ---------------------------------------------------------------------------
__device__ __forceinline__ void gemm_mainloop(
    uint32_t sbase, int tid, int lane, int wm, int wn,
    const __half* __restrict__ Ah, const __half* __restrict__ Al,
    const __half* __restrict__ Bm,
    int m0, int n0, int Ktot, float (&acc)[2][8][4])
{
    const int NCH = Ktot / 32;

    auto load_stage = [&](int ch, int st) {
        uint32_t sb = sbase + (uint32_t)st * 24576u;
        int kb = ch * 32;
        #pragma unroll
        for (int u = 0; u < 2; u++) {
            int idx = tid + u * 256;
            int row = idx >> 2, chunk = idx & 3;
            uint32_t soff = (uint32_t)(row * 64 + ((chunk ^ (row & 3)) * 16));
            size_t ga = (size_t)(m0 + row) * Ktot + kb + chunk * 8;
            size_t gb = (size_t)(n0 + row) * Ktot + kb + chunk * 8;
            CPA16(sb +          soff, (const void*)(Ah + ga));
            CPA16(sb +  8192u + soff, (const void*)(Al + ga));
            CPA16(sb + 16384u + soff, (const void*)(Bm + gb));
        }
    };

    auto compute_stage = [&](int st) {
        uint32_t sA = sbase + (uint32_t)st * 24576u;
        #pragma unroll
        for (int ks = 0; ks < 2; ks++) {
            uint32_t ah[2][4], al[2][4];
            #pragma unroll
            for (int mi = 0; mi < 2; mi++) {
                int r = wm * 32 + mi * 16 + (lane & 15);
                int c2 = ks * 2 + (lane >> 4);
                uint32_t off = (uint32_t)(r * 64 + ((c2 ^ (r & 3)) * 16));
                ldsm_x4(sA + off, ah[mi][0], ah[mi][1], ah[mi][2], ah[mi][3]);
                ldsm_x4(sA + 8192u + off, al[mi][0], al[mi][1], al[mi][2], al[mi][3]);
            }
            uint32_t bf[8][2];
            #pragma unroll
            for (int p = 0; p < 4; p++) {
                int r = wn * 64 + p * 16 + (lane & 15);
                int c2 = ks * 2 + (lane >> 4);
                uint32_t off = (uint32_t)(r * 64 + ((c2 ^ (r & 3)) * 16));
                uint32_t t0, t1, t2, t3;
                ldsm_x4(sA + 16384u + off, t0, t1, t2, t3);
                bf[2*p][0] = t0; bf[2*p][1] = t2; bf[2*p+1][0] = t1; bf[2*p+1][1] = t3;
            }
            #pragma unroll
            for (int mi = 0; mi < 2; mi++)
                #pragma unroll
                for (int ni = 0; ni < 8; ni++) {
                    mma_f16(acc[mi][ni], ah[mi], bf[ni]);
                    mma_f16(acc[mi][ni], al[mi], bf[ni]);
                }
        }
    };

    load_stage(0, 0); CP_COMMIT();
    load_stage(1, 1); CP_COMMIT();

    for (int ch = 0; ch < NCH; ch++) {
        CP_WAIT1();
        __syncthreads();
        compute_stage(ch & 1);
        __syncthreads();
        if (ch + 2 < NCH) load_stage(ch + 2, ch & 1);
        CP_COMMIT();
    }
}

// ---------------------------------------------------------------------------
// Fused QKV GEMM: bias + RoPE + outputs: Q split / K single / V^T single.
// V epilogue needs 66048 B smem -> GEMM_SMEM = 66560.
// ---------------------------------------------------------------------------
__global__ __launch_bounds__(256, 2)
void tc_gemm_qkv(const __half* __restrict__ Ah, const __half* __restrict__ Al,
                 const __half* __restrict__ Bm, const float* __restrict__ bias,
                 __half* __restrict__ Qh, __half* __restrict__ Ql,
                 __half* __restrict__ Kf, __half* __restrict__ Vt)
{
    extern __shared__ char smem[];
    uint32_t sbase = smem_u32(smem);
    int tid = threadIdx.x, lane = tid & 31, wid = tid >> 5;
    int wm = wid & 3, wn = wid >> 2;
    int m0 = blockIdx.y * 128, n0 = blockIdx.x * 128;

    float acc[2][8][4];
    #pragma unroll
    for (int mi = 0; mi < 2; mi++)
        #pragma unroll
        for (int ni = 0; ni < 8; ni++)
            #pragma unroll
            for (int e = 0; e < 4; e++) acc[mi][ni][e] = 0.f;

    gemm_mainloop(sbase, tid, lane, wm, wn, Ah, Al, Bm, m0, n0, E_, acc);
    __syncthreads();   // V branch reuses smem

    #pragma unroll
    for (int ni = 0; ni < 8; ni++) {
        int col = n0 + wn * 64 + ni * 8 + (lane & 3) * 2;
        float2 bv = *(const float2*)&bias[col];
        #pragma unroll
        for (int mi = 0; mi < 2; mi++) {
            acc[mi][ni][0] += bv.x; acc[mi][ni][1] += bv.y;
            acc[mi][ni][2] += bv.x; acc[mi][ni][3] += bv.y;
        }
    }

    int sec = n0 / 768;
    int nsec = n0 - sec * 768;
    int b = m0 >> 10;
    int t_base = m0 & 1023;

    if (sec < 2) {
        // ---- Q (split) or K (single): RoPE in registers ----
        int h = nsec / 64 + wn;
        int bh = b * H_ + h;
        float cs[8], sn[8];
        #pragma unroll
        for (int u = 0; u < 8; u++) {
            int d2 = (u >> 1) * 8 + (lane & 3) * 2 + (u & 1);
            float f = (float)h * exp2f(-(float)d2 * (13.287712379549449f / 32.0f));
            sincosf(f, &sn[u], &cs[u]);
        }
        const float scale = (sec == 0) ? 0.125f : 1.0f;

        #pragma unroll
        for (int mi = 0; mi < 2; mi++) {
            int rbase = wm * 32 + mi * 16 + (lane >> 2);
            #pragma unroll
            for (int eh = 0; eh < 2; eh++) {
                int t = t_base + rbase + eh * 8;
                size_t rowoff = ((size_t)bh * N_ + t) * (size_t)D_;
                #pragma unroll
                for (int ni = 0; ni < 4; ni++) {
                    float a0 = acc[mi][ni][eh*2+0], b0 = acc[mi][ni+4][eh*2+0];
                    float a1 = acc[mi][ni][eh*2+1], b1 = acc[mi][ni+4][eh*2+1];
                    int u0 = ni * 2, u1 = u0 + 1;
                    float lo0 = (a0 * cs[u0] - b0 * sn[u0]) * scale;
                    float hi0 = (b0 * cs[u0] + a0 * sn[u0]) * scale;
                    float lo1 = (a1 * cs[u1] - b1 * sn[u1]) * scale;
                    float hi1 = (b1 * cs[u1] + a1 * sn[u1]) * scale;
                    int d0 = ni * 8 + (lane & 3) * 2;
                    if (sec == 0) {
                        uint32_t H, L;
                        split2h(lo0, lo1, H, L);
                        *(uint32_t*)(Qh + rowoff + d0) = H;
                        *(uint32_t*)(Ql + rowoff + d0) = L;
                        split2h(hi0, hi1, H, L);
                        *(uint32_t*)(Qh + rowoff + d0 + 32) = H;
                        *(uint32_t*)(Ql + rowoff + d0 + 32) = L;
                    } else {
                        *(uint32_t*)(Kf + rowoff + d0)      = packh2(lo0, lo1);
                        *(uint32_t*)(Kf + rowoff + d0 + 32) = packh2(hi0, hi1);
                    }
                }
            }
        }
    } else {
        // ---- V: transpose via smem, single fp16, [bh][d][t] ----
        float* sv = (float*)smem;
        #pragma unroll
        for (int mi = 0; mi < 2; mi++)
            #pragma unroll
            for (int ni = 0; ni < 8; ni++)
                #pragma unroll
                for (int e = 0; e < 4; e++) {
                    int col = wn * 64 + ni * 8 + (lane & 3) * 2 + (e & 1);
                    int r = wm * 32 + mi * 16 + (lane >> 2) + ((e >> 1) * 8);
                    sv[col * 129 + r] = acc[mi][ni][e];
                }
        __syncthreads();
        for (int i = tid; i < 128 * 32; i += 256) {
            int col = i >> 5, t4 = (i & 31) * 4;
            float v0 = sv[col * 129 + t4 + 0];
            float v1 = sv[col * 129 + t4 + 1];
            float v2 = sv[col * 129 + t4 + 2];
            float v3 = sv[col * 129 + t4 + 3];
            int hv = nsec / 64 + (col >> 6);
            int d = col & 63;
            int bhv = b * H_ + hv;
            size_t ob = ((size_t)bhv * D_ + d) * (size_t)N_ + t_base + t4;
            uint2 Hv;
            Hv.x = packh2(v0, v1);
            Hv.y = packh2(v2, v3);
            *(uint2*)(Vt + ob) = Hv;
        }
    }
}

// ---------------------------------------------------------------------------
// Plain GEMM (projection): A split, B single, fp32 out + bias.
// ---------------------------------------------------------------------------
__global__ __launch_bounds__(256, 2)
void tc_gemm(const __half* __restrict__ Ah, const __half* __restrict__ Al,
             const __half* __restrict__ Bm, const float* __restrict__ bias,
             float* __restrict__ C, int Ntot, int Ktot)
{
    extern __shared__ char smem[];
    uint32_t sbase = smem_u32(smem);
    int tid = threadIdx.x, lane = tid & 31, wid = tid >> 5;
    int wm = wid & 3, wn = wid >> 2;
    int m0 = blockIdx.y * 128, n0 = blockIdx.x * 128;

    float acc[2][8][4];
    #pragma unroll
    for (int mi = 0; mi < 2; mi++)
        #pragma unroll
        for (int ni = 0; ni < 8; ni++)
            #pragma unroll
            for (int e = 0; e < 4; e++) acc[mi][ni][e] = 0.f;

    gemm_mainloop(sbase, tid, lane, wm, wn, Ah, Al, Bm, m0, n0, Ktot, acc);

    #pragma unroll
    for (int mi = 0; mi < 2; mi++) {
        #pragma unroll
        for (int ni = 0; ni < 8; ni++) {
            int row = m0 + wm * 32 + mi * 16 + (lane >> 2);
            int col = n0 + wn * 64 + ni * 8 + (lane & 3) * 2;
            float2 bv = *(const float2*)&bias[col];
            float2 v0 = {acc[mi][ni][0] + bv.x, acc[mi][ni][1] + bv.y};
            float2 v1 = {acc[mi][ni][2] + bv.x, acc[mi][ni][3] + bv.y};
            *(float2*)&C[(size_t)row * Ntot + col] = v0;
            *(float2*)&C[(size_t)(row + 8) * Ntot + col] = v1;
        }
    }
}

// ---------------------------------------------------------------------------
// Tensor-core flash attention (fp16 2-term): Q split / K single / V single.
// Smem: Qh@0 (16K), Ql@16K (16K), stage st @ 32K + st*16K: K@+0, V@+8K.
// Total 64KB, occupancy 2. R5 schedule (2-stage, two syncs).
// ---------------------------------------------------------------------------
__global__ __launch_bounds__(256, 2) void attn_mma(
    const __half* __restrict__ Qh, const __half* __restrict__ Ql,
    const __half* __restrict__ Kf, const __half* __restrict__ Vt,
    __half* __restrict__ Oh, __half* __restrict__ Ol)
{
    extern __shared__ char smem[];
    uint32_t sb = smem_u32(smem);
    const uint32_t oQh = 0, oQl = 16384, oStage = 32768;

    int tid = threadIdx.x, lane = tid & 31, wq = tid >> 5;
    int bh = blockIdx.y;
    int q0 = blockIdx.x * 128;
    int b = bh / H_, h = bh % H_;

    const __half* Qhb = Qh + ((size_t)bh * N_ + q0) * D_;
    const __half* Qlb = Ql + ((size_t)bh * N_ + q0) * D_;
    const __half* Kb  = Kf + (size_t)bh * N_ * D_;
    const __half* Vb  = Vt + (size_t)bh * D_ * N_;

    // Q load (both splits): 2048 16B chunks
    for (int u = tid; u < 2048; u += 256) {
        int split = u >> 10;
        int idx = u & 1023;
        int r = idx >> 3, chunk = idx & 7;
        uint32_t off = (uint32_t)(r * 128 + ((chunk ^ (r & 7)) * 16));
        const __half* src = (split ? Qlb : Qhb) + (size_t)r * D_ + chunk * 8;
        CPA16(sb + (split ? oQl : oQh) + off, (const void*)src);
    }

    auto load_stage = [&](int it, int st) {
        int jt = it * 64;
        uint32_t s0 = sb + oStage + (uint32_t)st * 16384u;
        for (int u = tid; u < 1024; u += 256) {
            int part = u >> 9;             // 0 = K, 1 = V
            int idx = u & 511;
            int r = idx >> 3, chunk = idx & 7;
            uint32_t off = (uint32_t)(r * 128 + ((chunk ^ (r & 7)) * 16));
            const __half* src = (part == 0)
                ? Kb + (size_t)(jt + r) * D_ + chunk * 8
                : Vb + (size_t)r * N_ + jt + chunk * 8;
            CPA16(s0 + (uint32_t)part * 8192u + off, (const void*)src);
        }
    };

    float o[8][4];
    #pragma unroll
    for (int i = 0; i < 8; i++)
        #pragma unroll
        for (int j = 0; j < 4; j++) o[i][j] = 0.f;
    float m0v = -1e30f, m1v = -1e30f, l0 = 0.f, l1 = 0.f;

    load_stage(0, 0); CP_COMMIT();
    load_stage(1, 1); CP_COMMIT();

    for (int it = 0; it < 16; it++) {
        CP_WAIT1();
        __syncthreads();
        uint32_t sK = sb + oStage + (uint32_t)(it & 1) * 16384u;

        float c[8][4];
        #pragma unroll
        for (int i = 0; i < 8; i++)
            #pragma unroll
            for (int j = 0; j < 4; j++) c[i][j] = 0.f;

        // ---- S = Q K^T: per ks: ldsm qh,ql + 4 K ldsm, 16 MMAs ----
        #pragma unroll
        for (int ks = 0; ks < 4; ks++) {
            int chunk = ks * 2 + (lane >> 4);
            int rq = wq * 16 + (lane & 15);
            uint32_t offq = (uint32_t)(rq * 128 + ((chunk ^ (rq & 7)) * 16));
            uint32_t ah[4], al[4];
            ldsm_x4(sb + oQh + offq, ah[0], ah[1], ah[2], ah[3]);
            ldsm_x4(sb + oQl + offq, al[0], al[1], al[2], al[3]);
            uint32_t bf[8][2];
            #pragma unroll
            for (int p = 0; p < 4; p++) {
                int rk = p * 16 + (lane & 15);
                uint32_t offk = (uint32_t)(rk * 128 + ((chunk ^ (rk & 7)) * 16));
                uint32_t t0, t1, t2, t3;
                ldsm_x4(sK + offk, t0, t1, t2, t3);
                bf[2*p][0] = t0; bf[2*p][1] = t2; bf[2*p+1][0] = t1; bf[2*p+1][1] = t3;
            }
            #pragma unroll
            for (int nt = 0; nt < 8; nt++) mma_f16(c[nt], ah, bf[nt]);
            #pragma unroll
            for (int nt = 0; nt < 8; nt++) mma_f16(c[nt], al, bf[nt]);
        }

        // ---- online softmax ----
        {
            float mt0 = -1e30f, mt1 = -1e30f;
            #pragma unroll
            for (int t = 0; t < 8; t++) {
                mt0 = fmaxf(mt0, fmaxf(c[t][0], c[t][1]));
                mt1 = fmaxf(mt1, fmaxf(c[t][2], c[t][3]));
            }
            mt0 = fmaxf(mt0, __shfl_xor_sync(0xffffffffu, mt0, 1));
            mt0 = fmaxf(mt0, __shfl_xor_sync(0xffffffffu, mt0, 2));
            mt1 = fmaxf(mt1, __shfl_xor_sync(0xffffffffu, mt1, 1));
            mt1 = fmaxf(mt1, __shfl_xor_sync(0xffffffffu, mt1, 2));
            float mn0 = fmaxf(m0v, mt0), mn1 = fmaxf(m1v, mt1);
            float f0 = __expf(m0v - mn0), f1 = __expf(m1v - mn1);
            m0v = mn0; m1v = mn1;
            float ps0 = 0.f, ps1 = 0.f;
            #pragma unroll
            for (int t = 0; t < 8; t++) {
                c[t][0] = __expf(c[t][0] - mn0); ps0 += c[t][0];
                c[t][1] = __expf(c[t][1] - mn0); ps0 += c[t][1];
                c[t][2] = __expf(c[t][2] - mn1); ps1 += c[t][2];
                c[t][3] = __expf(c[t][3] - mn1); ps1 += c[t][3];
            }
            ps0 += __shfl_xor_sync(0xffffffffu, ps0, 1);
            ps0 += __shfl_xor_sync(0xffffffffu, ps0, 2);
            ps1 += __shfl_xor_sync(0xffffffffu, ps1, 1);
            ps1 += __shfl_xor_sync(0xffffffffu, ps1, 2);
            l0 = l0 * f0 + ps0;
            l1 = l1 * f1 + ps1;
            #pragma unroll
            for (int t = 0; t < 8; t++) {
                o[t][0] *= f0; o[t][1] *= f0;
                o[t][2] *= f1; o[t][3] *= f1;
            }
        }

        // ---- P fragments (split hi/lo, exact) ----
        uint32_t aph[4][4], apl[4][4];
        #pragma unroll
        for (int s = 0; s < 4; s++) {
            #pragma unroll
            for (int half = 0; half < 2; half++) {
                int t = 2 * s + half;
                split2h(c[t][0], c[t][1], aph[s][half*2+0], apl[s][half*2+0]);
                split2h(c[t][2], c[t][3], aph[s][half*2+1], apl[s][half*2+1]);
            }
        }

        // ---- O += P V: per s: 4 V ldsm, 16 MMAs ----
        #pragma unroll
        for (int s = 0; s < 4; s++) {
            int chunk = s * 2 + (lane >> 4);
            uint32_t bf[8][2];
            #pragma unroll
            for (int p = 0; p < 4; p++) {
                int rd = p * 16 + (lane & 15);
                uint32_t off = (uint32_t)(rd * 128 + ((chunk ^ (rd & 7)) * 16));
                uint32_t t0, t1, t2, t3;
                ldsm_x4(sK + 8192u + off, t0, t1, t2, t3);
                bf[2*p][0] = t0; bf[2*p][1] = t2; bf[2*p+1][0] = t1; bf[2*p+1][1] = t3;
            }
            #pragma unroll
            for (int nt = 0; nt < 8; nt++) mma_f16(o[nt], aph[s], bf[nt]);
            #pragma unroll
            for (int nt = 0; nt < 8; nt++) mma_f16(o[nt], apl[s], bf[nt]);
        }

        __syncthreads();
        if (it + 2 < 16) load_stage(it + 2, it & 1);
        CP_COMMIT();
    }

    // epilogue: normalize + fp16 hi/lo split (exact A-side of proj)
    float inv0 = 1.0f / l0, inv1 = 1.0f / l1;
    int r = lane >> 2;
    int row0 = q0 + wq * 16 + r;
    size_t base0 = ((size_t)(b * N_) + row0) * E_ + h * 64 + (lane & 3) * 2;
    size_t base1 = base0 + (size_t)8 * E_;
    #pragma unroll
    for (int t = 0; t < 8; t++) {
        uint32_t H, L;
        split2h(o[t][0] * inv0, o[t][1] * inv0, H, L);
        *(uint32_t*)(Oh + base0 + t * 8) = H;
        *(uint32_t*)(Ol + base0 + t * 8) = L;
        split2h(o[t][2] * inv1, o[t][3] * inv1, H, L);
        *(uint32_t*)(Oh + base1 + t * 8) = H;
        *(uint32_t*)(Ol + base1 + t * 8) = L;
    }
}

// ---------------------------------------------------------------------------
extern "C" void kernel_launch(void* const* d_in, const int* in_sizes, int n_in,
                              void* d_out, int out_size)
{
    (void)in_sizes; (void)n_in; (void)out_size;
    const float* x      = (const float*)d_in[0];
    const float* w_qkv  = (const float*)d_in[1];
    const float* b_qkv  = (const float*)d_in[2];
    const float* w_proj = (const float*)d_in[3];
    const float* b_proj = (const float*)d_in[4];
    float* out = (float*)d_out;

    __half *xh, *xl, *wq, *wp, *aoh, *aol, *qh2, *ql2, *k2, *vt;
    cudaGetSymbolAddress((void**)&xh,  g_xh);
    cudaGetSymbolAddress((void**)&xl,  g_xl);
    cudaGetSymbolAddress((void**)&wq,  g_wq);
    cudaGetSymbolAddress((void**)&wp,  g_wp);
    cudaGetSymbolAddress((void**)&aoh, g_aoh);
    cudaGetSymbolAddress((void**)&aol, g_aol);
    cudaGetSymbolAddress((void**)&qh2, g_qh2);
    cudaGetSymbolAddress((void**)&ql2, g_ql2);
    cudaGetSymbolAddress((void**)&k2,  g_k2);
    cudaGetSymbolAddress((void**)&vt,  g_vt);

    // 66560 B: covers 2x24KB double-buffer AND the 66048 B V-transpose buffer.
    const int GEMM_SMEM = 66560;
    cudaFuncSetAttribute(tc_gemm_qkv, cudaFuncAttributeMaxDynamicSharedMemorySize, GEMM_SMEM);
    cudaFuncSetAttribute(tc_gemm, cudaFuncAttributeMaxDynamicSharedMemorySize, GEMM_SMEM);
    const int ATTN_SMEM = 65536;   // Q 32K + 2 stages x 16K
    cudaFuncSetAttribute(attn_mma, cudaFuncAttributeMaxDynamicSharedMemorySize, ATTN_SMEM);

    {
        int n4 = M_ * E_ / 4;
        convert_split<<<(n4 + 255) / 256, 256>>>((const float4*)x, (uint2*)xh, (uint2*)xl, n4);
    }
    {
        dim3 blk(32, 8);
        convert_w_t<<<dim3(3 * E_ / 32, E_ / 32), blk>>>(w_qkv, wq, E_, 3 * E_);
        convert_w_t<<<dim3(E_ / 32, E_ / 32), blk>>>(w_proj, wp, E_, E_);
    }
    {
        dim3 grid(3 * E_ / 128, M_ / 128);
        tc_gemm_qkv<<<grid, 256, GEMM_SMEM>>>(xh, xl, wq, b_qkv, qh2, ql2, k2, vt);
    }
    {
        dim3 grid(N_ / 128, B_ * H_);
        attn_mma<<<grid, 256, ATTN_SMEM>>>(qh2, ql2, k2, vt, aoh, aol);
    }
    {
        dim3 grid(E_ / 128, M_ / 128);
        tc_gemm<<<grid, 256, GEMM_SMEM>>>(aoh, aol, wp, b_proj, out, E_, E_);
    }
}

// round 11
// speedup vs baseline: 2.3138x; 1.5716x over previous
#include <cuda_runtime.h>
#include <cuda_fp16.h>
#include <math.h>
#include <stdint.h>

#define B_ 8
#define N_ 1024
#define E_ 768
#define H_ 12
#define D_ 64
#define M_ (B_*N_)   // 8192

// ---------------------------------------------------------------------------
// Scratch (__device__ globals; no allocations allowed)
// ---------------------------------------------------------------------------
__device__ __half g_x[(size_t)M_ * E_];           // x fp16
__device__ __half g_wq[(size_t)3*E_ * E_];        // w_qkv^T fp16
__device__ __half g_wp[(size_t)E_ * E_];          // w_proj^T fp16
__device__ __half g_ao[(size_t)M_ * E_];          // attention out fp16
__device__ __half g_q2[(size_t)B_*H_*N_*D_];      // Q (roped, scaled) fp16
__device__ __half g_k2[(size_t)B_*H_*N_*D_];      // K fp16
__device__ __half g_vt[(size_t)B_*H_*D_*N_];      // V^T fp16

// ---------------------------------------------------------------------------
// PTX helpers
// ---------------------------------------------------------------------------
__device__ __forceinline__ uint32_t smem_u32(const void* p) {
    uint32_t a;
    asm("{ .reg .u64 t; cvta.to.shared.u64 t, %1; cvt.u32.u64 %0, t; }" : "=r"(a) : "l"(p));
    return a;
}
#define CPA16(dst, src) \
    asm volatile("cp.async.cg.shared.global [%0], [%1], 16;" :: "r"(dst), "l"(src) : "memory")
#define CP_COMMIT() asm volatile("cp.async.commit_group;" ::: "memory")
#define CP_WAIT1()  asm volatile("cp.async.wait_group 1;" ::: "memory")

__device__ __forceinline__ void ldsm_x4(uint32_t addr, uint32_t& r0, uint32_t& r1,
                                        uint32_t& r2, uint32_t& r3) {
    asm volatile("ldmatrix.sync.aligned.m8n8.x4.shared.b16 {%0,%1,%2,%3}, [%4];"
                 : "=r"(r0), "=r"(r1), "=r"(r2), "=r"(r3) : "r"(addr));
}
__device__ __forceinline__ void mma_f16(float* c, const uint32_t* a, const uint32_t* b) {
    asm volatile("mma.sync.aligned.m16n8k16.row.col.f32.f16.f16.f32 "
        "{%0,%1,%2,%3}, {%4,%5,%6,%7}, {%8,%9}, {%0,%1,%2,%3};"
        : "+f"(c[0]), "+f"(c[1]), "+f"(c[2]), "+f"(c[3])
        : "r"(a[0]), "r"(a[1]), "r"(a[2]), "r"(a[3]), "r"(b[0]), "r"(b[1]));
}
__device__ __forceinline__ uint32_t packh2(float a, float b) {
    __half2 t = __floats2half2_rn(a, b);
    return *(uint32_t*)&t;
}

// ---------------------------------------------------------------------------
// convert kernels
// ---------------------------------------------------------------------------
__global__ void convert_h(const float4* __restrict__ in, uint2* __restrict__ outp, int n4)
{
    int i = blockIdx.x * blockDim.x + threadIdx.x;
    if (i >= n4) return;
    float4 v = in[i];
    uint2 H;
    H.x = packh2(v.x, v.y);
    H.y = packh2(v.z, v.w);
    outp[i] = H;
}

// W [K,N] fp32 -> W^T [N,K] fp16
__global__ void convert_w_t(const float* __restrict__ W,
                            __half* __restrict__ T, int K, int N)
{
    __shared__ float tile[32][33];
    int n0 = blockIdx.x * 32, k0 = blockIdx.y * 32;
    int tx = threadIdx.x, ty = threadIdx.y;
    for (int i = ty; i < 32; i += 8)
        tile[i][tx] = W[(size_t)(k0 + i) * N + n0 + tx];
    __syncthreads();
    for (int i = ty; i < 32; i += 8)
        T[(size_t)(n0 + i) * K + k0 + tx] = __float2half_rn(tile[tx][i]);
}

// ---------------------------------------------------------------------------
// GEMM mainloop (2-stage, two syncs). Single fp16 A and B.
// Smem per stage 16KB: A@0, B@8K. 8 warps, warp tile 32x64.
// Per chunk per warp: 12 LDSM, 32 MMAs.
// ---------------------------------------------------------------------------
__device__ __forceinline__ void gemm_mainloop(
    uint32_t sbase, int tid, int lane, int wm, int wn,
    const __half* __restrict__ Am, const __half* __restrict__ Bm,
    int m0, int n0, int Ktot, float (&acc)[2][8][4])
{
    const int NCH = Ktot / 32;

    auto load_stage = [&](int ch, int st) {
        uint32_t sb = sbase + (uint32_t)st * 16384u;
        int kb = ch * 32;
        #pragma unroll
        for (int u = 0; u < 2; u++) {
            int idx = tid + u * 256;
            int row = idx >> 2, chunk = idx & 3;
            uint32_t soff = (uint32_t)(row * 64 + ((chunk ^ (row & 3)) * 16));
            size_t ga = (size_t)(m0 + row) * Ktot + kb + chunk * 8;
            size_t gb = (size_t)(n0 + row) * Ktot + kb + chunk * 8;
            CPA16(sb +         soff, (const void*)(Am + ga));
            CPA16(sb + 8192u + soff, (const void*)(Bm + gb));
        }
    };

    auto compute_stage = [&](int st) {
        uint32_t sA = sbase + (uint32_t)st * 16384u;
        #pragma unroll
        for (int ks = 0; ks < 2; ks++) {
            uint32_t af[2][4];
            #pragma unroll
            for (int mi = 0; mi < 2; mi++) {
                int r = wm * 32 + mi * 16 + (lane & 15);
                int c2 = ks * 2 + (lane >> 4);
                uint32_t off = (uint32_t)(r * 64 + ((c2 ^ (r & 3)) * 16));
                ldsm_x4(sA + off, af[mi][0], af[mi][1], af[mi][2], af[mi][3]);
            }
            uint32_t bf[8][2];
            #pragma unroll
            for (int p = 0; p < 4; p++) {
                int r = wn * 64 + p * 16 + (lane & 15);
                int c2 = ks * 2 + (lane >> 4);
                uint32_t off = (uint32_t)(r * 64 + ((c2 ^ (r & 3)) * 16));
                uint32_t t0, t1, t2, t3;
                ldsm_x4(sA + 8192u + off, t0, t1, t2, t3);
                bf[2*p][0] = t0; bf[2*p][1] = t2; bf[2*p+1][0] = t1; bf[2*p+1][1] = t3;
            }
            #pragma unroll
            for (int mi = 0; mi < 2; mi++)
                #pragma unroll
                for (int ni = 0; ni < 8; ni++)
                    mma_f16(acc[mi][ni], af[mi], bf[ni]);
        }
    };

    load_stage(0, 0); CP_COMMIT();
    load_stage(1, 1); CP_COMMIT();

    for (int ch = 0; ch < NCH; ch++) {
        CP_WAIT1();
        __syncthreads();
        compute_stage(ch & 1);
        __syncthreads();
        if (ch + 2 < NCH) load_stage(ch + 2, ch & 1);
        CP_COMMIT();
    }
}

// ---------------------------------------------------------------------------
// Fused QKV GEMM: bias + RoPE; outputs Q/K fp16 [bh][t][64], V^T fp16 [bh][d][t].
// V epilogue needs 66048 B smem -> GEMM_SMEM = 66560.
// ---------------------------------------------------------------------------
__global__ __launch_bounds__(256, 2)
void tc_gemm_qkv(const __half* __restrict__ Am, const __half* __restrict__ Bm,
                 const float* __restrict__ bias,
                 __half* __restrict__ Qf, __half* __restrict__ Kf,
                 __half* __restrict__ Vt)
{
    extern __shared__ char smem[];
    uint32_t sbase = smem_u32(smem);
    int tid = threadIdx.x, lane = tid & 31, wid = tid >> 5;
    int wm = wid & 3, wn = wid >> 2;
    int m0 = blockIdx.y * 128, n0 = blockIdx.x * 128;

    float acc[2][8][4];
    #pragma unroll
    for (int mi = 0; mi < 2; mi++)
        #pragma unroll
        for (int ni = 0; ni < 8; ni++)
            #pragma unroll
            for (int e = 0; e < 4; e++) acc[mi][ni][e] = 0.f;

    gemm_mainloop(sbase, tid, lane, wm, wn, Am, Bm, m0, n0, E_, acc);
    __syncthreads();   // V branch reuses smem

    #pragma unroll
    for (int ni = 0; ni < 8; ni++) {
        int col = n0 + wn * 64 + ni * 8 + (lane & 3) * 2;
        float2 bv = *(const float2*)&bias[col];
        #pragma unroll
        for (int mi = 0; mi < 2; mi++) {
            acc[mi][ni][0] += bv.x; acc[mi][ni][1] += bv.y;
            acc[mi][ni][2] += bv.x; acc[mi][ni][3] += bv.y;
        }
    }

    int sec = n0 / 768;
    int nsec = n0 - sec * 768;
    int b = m0 >> 10;
    int t_base = m0 & 1023;

    if (sec < 2) {
        // ---- Q or K: RoPE in registers, single fp16 out ----
        int h = nsec / 64 + wn;
        int bh = b * H_ + h;
        float cs[8], sn[8];
        #pragma unroll
        for (int u = 0; u < 8; u++) {
            int d2 = (u >> 1) * 8 + (lane & 3) * 2 + (u & 1);
            float f = (float)h * exp2f(-(float)d2 * (13.287712379549449f / 32.0f));
            sincosf(f, &sn[u], &cs[u]);
        }
        __half* Of = (sec == 0) ? Qf : Kf;
        const float scale = (sec == 0) ? 0.125f : 1.0f;

        #pragma unroll
        for (int mi = 0; mi < 2; mi++) {
            int rbase = wm * 32 + mi * 16 + (lane >> 2);
            #pragma unroll
            for (int eh = 0; eh < 2; eh++) {
                int t = t_base + rbase + eh * 8;
                size_t rowoff = ((size_t)bh * N_ + t) * (size_t)D_;
                #pragma unroll
                for (int ni = 0; ni < 4; ni++) {
                    float a0 = acc[mi][ni][eh*2+0], b0 = acc[mi][ni+4][eh*2+0];
                    float a1 = acc[mi][ni][eh*2+1], b1 = acc[mi][ni+4][eh*2+1];
                    int u0 = ni * 2, u1 = u0 + 1;
                    float lo0 = (a0 * cs[u0] - b0 * sn[u0]) * scale;
                    float hi0 = (b0 * cs[u0] + a0 * sn[u0]) * scale;
                    float lo1 = (a1 * cs[u1] - b1 * sn[u1]) * scale;
                    float hi1 = (b1 * cs[u1] + a1 * sn[u1]) * scale;
                    int d0 = ni * 8 + (lane & 3) * 2;
                    *(uint32_t*)(Of + rowoff + d0)      = packh2(lo0, lo1);
                    *(uint32_t*)(Of + rowoff + d0 + 32) = packh2(hi0, hi1);
                }
            }
        }
    } else {
        // ---- V: transpose via smem, fp16, [bh][d][t] ----
        float* sv = (float*)smem;
        #pragma unroll
        for (int mi = 0; mi < 2; mi++)
            #pragma unroll
            for (int ni = 0; ni < 8; ni++)
                #pragma unroll
                for (int e = 0; e < 4; e++) {
                    int col = wn * 64 + ni * 8 + (lane & 3) * 2 + (e & 1);
                    int r = wm * 32 + mi * 16 + (lane >> 2) + ((e >> 1) * 8);
                    sv[col * 129 + r] = acc[mi][ni][e];
                }
        __syncthreads();
        for (int i = tid; i < 128 * 32; i += 256) {
            int col = i >> 5, t4 = (i & 31) * 4;
            float v0 = sv[col * 129 + t4 + 0];
            float v1 = sv[col * 129 + t4 + 1];
            float v2 = sv[col * 129 + t4 + 2];
            float v3 = sv[col * 129 + t4 + 3];
            int hv = nsec / 64 + (col >> 6);
            int d = col & 63;
            int bhv = b * H_ + hv;
            size_t ob = ((size_t)bhv * D_ + d) * (size_t)N_ + t_base + t4;
            uint2 Hv;
            Hv.x = packh2(v0, v1);
            Hv.y = packh2(v2, v3);
            *(uint2*)(Vt + ob) = Hv;
        }
    }
}

// ---------------------------------------------------------------------------
// Plain GEMM (projection): fp16 A/B, fp32 out + bias.
// ---------------------------------------------------------------------------
__global__ __launch_bounds__(256, 2)
void tc_gemm(const __half* __restrict__ Am, const __half* __restrict__ Bm,
             const float* __restrict__ bias, float* __restrict__ C,
             int Ntot, int Ktot)
{
    extern __shared__ char smem[];
    uint32_t sbase = smem_u32(smem);
    int tid = threadIdx.x, lane = tid & 31, wid = tid >> 5;
    int wm = wid & 3, wn = wid >> 2;
    int m0 = blockIdx.y * 128, n0 = blockIdx.x * 128;

    float acc[2][8][4];
    #pragma unroll
    for (int mi = 0; mi < 2; mi++)
        #pragma unroll
        for (int ni = 0; ni < 8; ni++)
            #pragma unroll
            for (int e = 0; e < 4; e++) acc[mi][ni][e] = 0.f;

    gemm_mainloop(sbase, tid, lane, wm, wn, Am, Bm, m0, n0, Ktot, acc);

    #pragma unroll
    for (int mi = 0; mi < 2; mi++) {
        #pragma unroll
        for (int ni = 0; ni < 8; ni++) {
            int row = m0 + wm * 32 + mi * 16 + (lane >> 2);
            int col = n0 + wn * 64 + ni * 8 + (lane & 3) * 2;
            float2 bv = *(const float2*)&bias[col];
            float2 v0 = {acc[mi][ni][0] + bv.x, acc[mi][ni][1] + bv.y};
            float2 v1 = {acc[mi][ni][2] + bv.x, acc[mi][ni][3] + bv.y};
            *(float2*)&C[(size_t)row * Ntot + col] = v0;
            *(float2*)&C[(size_t)(row + 8) * Ntot + col] = v1;
        }
    }
}

// ---------------------------------------------------------------------------
// Tensor-core flash attention (single fp16): Q/K/V fp16.
// Smem: Q@0 (16K), stage st @ 16K + st*16K: K@+0, V@+8K. Total 48KB, occ 2.
// ---------------------------------------------------------------------------
__global__ __launch_bounds__(256, 2) void attn_mma(
    const __half* __restrict__ Qf, const __half* __restrict__ Kf,
    const __half* __restrict__ Vt, __half* __restrict__ Oo)
{
    extern __shared__ char smem[];
    uint32_t sb = smem_u32(smem);
    const uint32_t oQ = 0, oStage = 16384;

    int tid = threadIdx.x, lane = tid & 31, wq = tid >> 5;
    int bh = blockIdx.y;
    int q0 = blockIdx.x * 128;
    int b = bh / H_, h = bh % H_;

    const __half* Qb = Qf + ((size_t)bh * N_ + q0) * D_;
    const __half* Kb = Kf + (size_t)bh * N_ * D_;
    const __half* Vb = Vt + (size_t)bh * D_ * N_;

    // Q load: 1024 16B chunks
    for (int u = tid; u < 1024; u += 256) {
        int r = u >> 3, chunk = u & 7;
        uint32_t off = (uint32_t)(r * 128 + ((chunk ^ (r & 7)) * 16));
        CPA16(sb + oQ + off, (const void*)(Qb + (size_t)r * D_ + chunk * 8));
    }

    auto load_stage = [&](int it, int st) {
        int jt = it * 64;
        uint32_t s0 = sb + oStage + (uint32_t)st * 16384u;
        for (int u = tid; u < 1024; u += 256) {
            int part = u >> 9;             // 0 = K, 1 = V
            int idx = u & 511;
            int r = idx >> 3, chunk = idx & 7;
            uint32_t off = (uint32_t)(r * 128 + ((chunk ^ (r & 7)) * 16));
            const __half* src = (part == 0)
                ? Kb + (size_t)(jt + r) * D_ + chunk * 8
                : Vb + (size_t)r * N_ + jt + chunk * 8;
            CPA16(s0 + (uint32_t)part * 8192u + off, (const void*)src);
        }
    };

    float o[8][4];
    #pragma unroll
    for (int i = 0; i < 8; i++)
        #pragma unroll
        for (int j = 0; j < 4; j++) o[i][j] = 0.f;
    float m0v = -1e30f, m1v = -1e30f, l0 = 0.f, l1 = 0.f;

    load_stage(0, 0); CP_COMMIT();
    load_stage(1, 1); CP_COMMIT();

    for (int it = 0; it < 16; it++) {
        CP_WAIT1();
        __syncthreads();
        uint32_t sK = sb + oStage + (uint32_t)(it & 1) * 16384u;

        float c[8][4];
        #pragma unroll
        for (int i = 0; i < 8; i++)
            #pragma unroll
            for (int j = 0; j < 4; j++) c[i][j] = 0.f;

        // ---- S = Q K^T ----
        #pragma unroll
        for (int ks = 0; ks < 4; ks++) {
            int chunk = ks * 2 + (lane >> 4);
            int rq = wq * 16 + (lane & 15);
            uint32_t offq = (uint32_t)(rq * 128 + ((chunk ^ (rq & 7)) * 16));
            uint32_t af[4];
            ldsm_x4(sb + oQ + offq, af[0], af[1], af[2], af[3]);
            uint32_t bf[8][2];
            #pragma unroll
            for (int p = 0; p < 4; p++) {
                int rk = p * 16 + (lane & 15);
                uint32_t offk = (uint32_t)(rk * 128 + ((chunk ^ (rk & 7)) * 16));
                uint32_t t0, t1, t2, t3;
                ldsm_x4(sK + offk, t0, t1, t2, t3);
                bf[2*p][0] = t0; bf[2*p][1] = t2; bf[2*p+1][0] = t1; bf[2*p+1][1] = t3;
            }
            #pragma unroll
            for (int nt = 0; nt < 8; nt++) mma_f16(c[nt], af, bf[nt]);
        }

        // ---- online softmax ----
        {
            float mt0 = -1e30f, mt1 = -1e30f;
            #pragma unroll
            for (int t = 0; t < 8; t++) {
                mt0 = fmaxf(mt0, fmaxf(c[t][0], c[t][1]));
                mt1 = fmaxf(mt1, fmaxf(c[t][2], c[t][3]));
            }
            mt0 = fmaxf(mt0, __shfl_xor_sync(0xffffffffu, mt0, 1));
            mt0 = fmaxf(mt0, __shfl_xor_sync(0xffffffffu, mt0, 2));
            mt1 = fmaxf(mt1, __shfl_xor_sync(0xffffffffu, mt1, 1));
            mt1 = fmaxf(mt1, __shfl_xor_sync(0xffffffffu, mt1, 2));
            float mn0 = fmaxf(m0v, mt0), mn1 = fmaxf(m1v, mt1);
            float f0 = __expf(m0v - mn0), f1 = __expf(m1v - mn1);
            m0v = mn0; m1v = mn1;
            float ps0 = 0.f, ps1 = 0.f;
            #pragma unroll
            for (int t = 0; t < 8; t++) {
                c[t][0] = __expf(c[t][0] - mn0); ps0 += c[t][0];
                c[t][1] = __expf(c[t][1] - mn0); ps0 += c[t][1];
                c[t][2] = __expf(c[t][2] - mn1); ps1 += c[t][2];
                c[t][3] = __expf(c[t][3] - mn1); ps1 += c[t][3];
            }
            ps0 += __shfl_xor_sync(0xffffffffu, ps0, 1);
            ps0 += __shfl_xor_sync(0xffffffffu, ps0, 2);
            ps1 += __shfl_xor_sync(0xffffffffu, ps1, 1);
            ps1 += __shfl_xor_sync(0xffffffffu, ps1, 2);
            l0 = l0 * f0 + ps0;
            l1 = l1 * f1 + ps1;
            #pragma unroll
            for (int t = 0; t < 8; t++) {
                o[t][0] *= f0; o[t][1] *= f0;
                o[t][2] *= f1; o[t][3] *= f1;
            }
        }

        // ---- P fragments (single fp16) ----
        uint32_t ap[4][4];
        #pragma unroll
        for (int s = 0; s < 4; s++) {
            #pragma unroll
            for (int half = 0; half < 2; half++) {
                int t = 2 * s + half;
                ap[s][half * 2 + 0] = packh2(c[t][0], c[t][1]);
                ap[s][half * 2 + 1] = packh2(c[t][2], c[t][3]);
            }
        }

        // ---- O += P V ----
        #pragma unroll
        for (int s = 0; s < 4; s++) {
            int chunk = s * 2 + (lane >> 4);
            uint32_t bf[8][2];
            #pragma unroll
            for (int p = 0; p < 4; p++) {
                int rd = p * 16 + (lane & 15);
                uint32_t off = (uint32_t)(rd * 128 + ((chunk ^ (rd & 7)) * 16));
                uint32_t t0, t1, t2, t3;
                ldsm_x4(sK + 8192u + off, t0, t1, t2, t3);
                bf[2*p][0] = t0; bf[2*p][1] = t2; bf[2*p+1][0] = t1; bf[2*p+1][1] = t3;
            }
            #pragma unroll
            for (int nt = 0; nt < 8; nt++) mma_f16(o[nt], ap[s], bf[nt]);
        }

        __syncthreads();
        if (it + 2 < 16) load_stage(it + 2, it & 1);
        CP_COMMIT();
    }

    // epilogue: normalize + single fp16 out
    float inv0 = 1.0f / l0, inv1 = 1.0f / l1;
    int r = lane >> 2;
    int row0 = q0 + wq * 16 + r;
    size_t base0 = ((size_t)(b * N_) + row0) * E_ + h * 64 + (lane & 3) * 2;
    size_t base1 = base0 + (size_t)8 * E_;
    #pragma unroll
    for (int t = 0; t < 8; t++) {
        *(uint32_t*)(Oo + base0 + t * 8) = packh2(o[t][0] * inv0, o[t][1] * inv0);
        *(uint32_t*)(Oo + base1 + t * 8) = packh2(o[t][2] * inv1, o[t][3] * inv1);
    }
}

// ---------------------------------------------------------------------------
extern "C" void kernel_launch(void* const* d_in, const int* in_sizes, int n_in,
                              void* d_out, int out_size)
{
    (void)in_sizes; (void)n_in; (void)out_size;
    const float* x      = (const float*)d_in[0];
    const float* w_qkv  = (const float*)d_in[1];
    const float* b_qkv  = (const float*)d_in[2];
    const float* w_proj = (const float*)d_in[3];
    const float* b_proj = (const float*)d_in[4];
    float* out = (float*)d_out;

    __half *xf, *wq, *wp, *ao, *q2, *k2, *vt;
    cudaGetSymbolAddress((void**)&xf, g_x);
    cudaGetSymbolAddress((void**)&wq, g_wq);
    cudaGetSymbolAddress((void**)&wp, g_wp);
    cudaGetSymbolAddress((void**)&ao, g_ao);
    cudaGetSymbolAddress((void**)&q2, g_q2);
    cudaGetSymbolAddress((void**)&k2, g_k2);
    cudaGetSymbolAddress((void**)&vt, g_vt);

    // 66560 B: covers 2x16KB double-buffer AND the 66048 B V-transpose buffer.
    const int GEMM_SMEM = 66560;
    cudaFuncSetAttribute(tc_gemm_qkv, cudaFuncAttributeMaxDynamicSharedMemorySize, GEMM_SMEM);
    cudaFuncSetAttribute(tc_gemm, cudaFuncAttributeMaxDynamicSharedMemorySize, GEMM_SMEM);
    const int ATTN_SMEM = 49152;   // Q 16K + 2 stages x 16K
    cudaFuncSetAttribute(attn_mma, cudaFuncAttributeMaxDynamicSharedMemorySize, ATTN_SMEM);

    {
        int n4 = M_ * E_ / 4;
        convert_h<<<(n4 + 255) / 256, 256>>>((const float4*)x, (uint2*)xf, n4);
    }
    {
        dim3 blk(32, 8);
        convert_w_t<<<dim3(3 * E_ / 32, E_ / 32), blk>>>(w_qkv, wq, E_, 3 * E_);
        convert_w_t<<<dim3(E_ / 32, E_ / 32), blk>>>(w_proj, wp, E_, E_);
    }
    {
        dim3 grid(3 * E_ / 128, M_ / 128);
        tc_gemm_qkv<<<grid, 256, GEMM_SMEM>>>(xf, wq, b_qkv, q2, k2, vt);
    }
    {
        dim3 grid(N_ / 128, B_ * H_);
        attn_mma<<<grid, 256, ATTN_SMEM>>>(q2, k2, vt, ao);
    }
    {
        dim3 grid(E_ / 128, M_ / 128);
        tc_gemm<<<grid, 256, GEMM_SMEM>>>(ao, wp, b_proj, out, E_, E_);
    }
}